// round 9
// baseline (speedup 1.0000x reference)
#include <cuda_runtime.h>
#include <cuda_fp16.h>
#include <cmath>

// Problem constants
#define BATCH   2
#define SEQ     2048
#define DIM     1024
#define NH      16
#define DKH     16
#define DVH     64
#define NTOK    (BATCH*SEQ)          // 4096
#define QCOLS   (NH*DKH)             // 256
#define KVCOLS  (NH*(DKH+DVH))       // 1280
#define OCOLS   (NH*DVH)             // 1024
#define PCOLS   1536                 // 256 q + 256 k + 1024 v (permuted)

// ---------------- scratch ----------------
__device__ __half g_tokh[NTOK * DIM];
__device__ __half g_wc  [PCOLS * DIM];
__device__ __half g_wot [DIM * OCOLS];
__device__ __half g_qn[BATCH*NH*SEQ*DKH];
__device__ __half g_kn[BATCH*NH*SEQ*DKH];
__device__ __half g_vh[BATCH*NH*SEQ*DVH];
__device__ __half g_aoh[NTOK * OCOLS];

// ---------------- helpers ----------------
__device__ __forceinline__ unsigned packh2(float a, float b){
    __half2 h = __floats2half2_rn(a, b);
    return *(unsigned*)&h;
}
__device__ __forceinline__ unsigned sptr(const void* p){
    return (unsigned)__cvta_generic_to_shared(p);
}
__device__ __forceinline__ void ldm4(unsigned r[4], unsigned a){
    asm volatile("ldmatrix.sync.aligned.m8n8.x4.shared.b16 {%0,%1,%2,%3}, [%4];"
        : "=r"(r[0]),"=r"(r[1]),"=r"(r[2]),"=r"(r[3]) : "r"(a));
}
__device__ __forceinline__ void ldm4t(unsigned r[4], unsigned a){
    asm volatile("ldmatrix.sync.aligned.m8n8.x4.trans.shared.b16 {%0,%1,%2,%3}, [%4];"
        : "=r"(r[0]),"=r"(r[1]),"=r"(r[2]),"=r"(r[3]) : "r"(a));
}
__device__ __forceinline__ void mma16(float* c, const unsigned* a, const unsigned* b){
    asm volatile("mma.sync.aligned.m16n8k16.row.col.f32.f16.f16.f32 "
        "{%0,%1,%2,%3},{%4,%5,%6,%7},{%8,%9},{%0,%1,%2,%3};\n"
        : "+f"(c[0]),"+f"(c[1]),"+f"(c[2]),"+f"(c[3])
        : "r"(a[0]),"r"(a[1]),"r"(a[2]),"r"(a[3]),"r"(b[0]),"r"(b[1]));
}
__device__ __forceinline__ void cpa16(unsigned dst, const void* src){
    asm volatile("cp.async.cg.shared.global [%0], [%1], 16;" :: "r"(dst), "l"(src));
}
#define CP_COMMIT() asm volatile("cp.async.commit_group;" ::: "memory")
#define CP_WAIT0()  asm volatile("cp.async.wait_group 0;" ::: "memory")
#define CP_WAIT1()  asm volatile("cp.async.wait_group 1;" ::: "memory")

// ---------------- prep kernels ----------------
__global__ __launch_bounds__(256) void cvt_f2h(const float* __restrict__ src,
                                              __half* __restrict__ dst, int n8)
{
    int i = blockIdx.x * blockDim.x + threadIdx.x;
    if (i >= n8) return;
    float4 a = ((const float4*)src)[2*i];
    float4 b = ((const float4*)src)[2*i+1];
    uint4 p = make_uint4(packh2(a.x,a.y), packh2(a.z,a.w),
                         packh2(b.x,b.y), packh2(b.z,b.w));
    ((uint4*)dst)[i] = p;
}

__global__ __launch_bounds__(256) void wprep(const float* __restrict__ Wq,
                                             const float* __restrict__ Wkv,
                                             __half* __restrict__ Wc)
{
    __shared__ float ts[32][33];
    const int n0 = blockIdx.x * 32, k0 = blockIdx.y * 32;
    const int tx = threadIdx.x & 31, ty = threadIdx.x >> 5;
    {
        const int n = n0 + tx;
        const float* W; int c, ld;
        if (n < 256)      { W = Wq;  ld = QCOLS;  c = n; }
        else if (n < 512) { int j = n - 256; W = Wkv; ld = KVCOLS; c = (j >> 4) * 80 + (j & 15); }
        else              { int j = n - 512; W = Wkv; ld = KVCOLS; c = (j >> 6) * 80 + 16 + (j & 63); }
        #pragma unroll
        for (int i = 0; i < 32; i += 8)
            ts[ty + i][tx] = W[(size_t)(k0 + ty + i) * ld + c];
    }
    __syncthreads();
    #pragma unroll
    for (int i = 0; i < 32; i += 8)
        Wc[(size_t)(n0 + ty + i) * DIM + k0 + tx] = __float2half(ts[tx][ty + i]);
}

__global__ __launch_bounds__(256) void wtrans(const float* __restrict__ W,
                                              __half* __restrict__ Wt, int N, int K)
{
    __shared__ float ts[32][33];
    const int n0 = blockIdx.x * 32, k0 = blockIdx.y * 32;
    const int tx = threadIdx.x & 31, ty = threadIdx.x >> 5;
    #pragma unroll
    for (int i = 0; i < 32; i += 8)
        ts[ty + i][tx] = W[(size_t)(k0 + ty + i) * N + n0 + tx];
    __syncthreads();
    #pragma unroll
    for (int i = 0; i < 32; i += 8)
        Wt[(size_t)(n0 + ty + i) * K + k0 + tx] = __float2half(ts[tx][ty + i]);
}

// ====== GEMM core: 128x64 block, 8 warps, warp 32x32, 3-stage pipeline =====
// BK=32 fp16. A[M][K], Bt[N][K] row-major fp16.
#define GAS 20
__shared__ struct { } _dummy_;   // (nothing)

#define CORE_LOAD(AP, BP, K_, k0_, st_) do {                                     \
    cpa16(sptr(&As[st_][ar][ac4*4]),     &(AP)[(size_t)(m0+ar)*(K_) + (k0_) + ac4*8]);     \
    cpa16(sptr(&As[st_][ar+64][ac4*4]),  &(AP)[(size_t)(m0+ar+64)*(K_) + (k0_) + ac4*8]);  \
    if (t < 256)                                                                 \
        cpa16(sptr(&Bs[st_][ar & 63][((t >> 6 & 1) * 0) + ac4*4]), /*placeholder*/ \
              &(BP)[(size_t)(n0+(ar & 63))*(K_) + (k0_) + ac4*8]);               \
} while(0)

// NOTE: B tile is 64 rows; use first 256 threads: row = t>>2 (0..63) for t<256
#undef CORE_LOAD
#define CORE_LOAD(AP, BP, K_, k0_, st_) do {                                     \
    cpa16(sptr(&As[st_][ar][ac4*4]),     &(AP)[(size_t)(m0+ar)*(K_) + (k0_) + ac4*8]);     \
    cpa16(sptr(&As[st_][ar+64][ac4*4]),  &(AP)[(size_t)(m0+ar+64)*(K_) + (k0_) + ac4*8]);  \
    cpa16(sptr(&Bs[st_][ar][ac4*4]),     &(BP)[(size_t)(n0+ar)*(K_) + (k0_) + ac4*8]);     \
} while(0)
// ar covers 0..63 exactly when t in [0,255]: ar = t>>2 gives 0..63. A needs 128
// rows -> two cpa16 (ar, ar+64). B needs 64 rows -> one cpa16 (ar).

#define CORE_COMPUTE(st_) do {                                                   \
    const unsigned oa = (st_) * (unsigned)sizeof(As[0]);                         \
    const unsigned ob = (st_) * (unsigned)sizeof(Bs[0]);                         \
    _Pragma("unroll")                                                            \
    for (int ks = 0; ks < 2; ks++) {                                             \
        const unsigned cb = ks * 32;                                             \
        unsigned a0[4], a1[4], b0[4], b1[4];                                     \
        ldm4(a0, adrA0 + oa + cb);                                               \
        ldm4(a1, adrA1 + oa + cb);                                               \
        ldm4(b0, adrB + ob + cb);                                                \
        ldm4(b1, adrB + ob + cb + 16);                                           \
        _Pragma("unroll")                                                        \
        for (int nt = 0; nt < 4; nt++) {                                         \
            unsigned bb[2] = { b0[nt], b1[nt] };                                 \
            mma16(Co[0][nt], a0, bb);                                            \
            mma16(Co[1][nt], a1, bb);                                            \
        }                                                                        \
    }                                                                            \
} while(0)

// ---------------- fused projection GEMM + l2norm + head scatter ------------
__global__ __launch_bounds__(256) void proj_gemm(
    const __half* __restrict__ A, const __half* __restrict__ Bt,
    __half* __restrict__ gq, __half* __restrict__ gk, __half* __restrict__ gv)
{
    __shared__ unsigned As[3][128][GAS];
    __shared__ unsigned Bs[3][64][GAS];
    __shared__ float sq[128][4];

    const int t = threadIdx.x;
    const int w = t >> 5, lane = t & 31, g = lane >> 2, tig = lane & 3;
    const int wm = (w >> 1) * 32, wn = (w & 1) * 32;
    const int m0 = blockIdx.y * 128, n0 = blockIdx.x * 64;
    const int li = lane & 7, lj = lane >> 3;
    const int ar = t >> 2, ac4 = t & 3;

    const unsigned adrA0 = sptr(&As[0][wm + (lj & 1) * 8 + li][(lj >> 1) * 4]);
    const unsigned adrA1 = adrA0 + 16 * GAS * 4;
    const unsigned adrB  = sptr(&Bs[0][wn + lj * 8 + li][0]);

    CORE_LOAD(A, Bt, DIM, 0, 0);  CP_COMMIT();
    CORE_LOAD(A, Bt, DIM, 32, 1); CP_COMMIT();

    float Co[2][4][4] = {};
    const int KT = DIM / 32;
    for (int kt = 0; kt < KT; kt++) {
        if (kt + 1 < KT) CP_WAIT1(); else CP_WAIT0();
        __syncthreads();
        if (kt + 2 < KT) { CORE_LOAD(A, Bt, DIM, (kt + 2) * 32, (kt + 2) % 3); CP_COMMIT(); }
        CORE_COMPUTE((unsigned)(kt % 3));
        __syncthreads();
    }

    // ---- epilogue: group sums of squares (smem table, R5-proven) ----
    #pragma unroll
    for (int mt = 0; mt < 2; mt++) {
        float pA0 = 0, pA1 = 0, pB0 = 0, pB1 = 0;
        #pragma unroll
        for (int nt = 0; nt < 2; nt++) {
            pA0 += Co[mt][nt][0]*Co[mt][nt][0] + Co[mt][nt][1]*Co[mt][nt][1];
            pA1 += Co[mt][nt][2]*Co[mt][nt][2] + Co[mt][nt][3]*Co[mt][nt][3];
            pB0 += Co[mt][nt+2][0]*Co[mt][nt+2][0] + Co[mt][nt+2][1]*Co[mt][nt+2][1];
            pB1 += Co[mt][nt+2][2]*Co[mt][nt+2][2] + Co[mt][nt+2][3]*Co[mt][nt+2][3];
        }
        pA0 += __shfl_xor_sync(~0u, pA0, 1); pA0 += __shfl_xor_sync(~0u, pA0, 2);
        pA1 += __shfl_xor_sync(~0u, pA1, 1); pA1 += __shfl_xor_sync(~0u, pA1, 2);
        pB0 += __shfl_xor_sync(~0u, pB0, 1); pB0 += __shfl_xor_sync(~0u, pB0, 2);
        pB1 += __shfl_xor_sync(~0u, pB1, 1); pB1 += __shfl_xor_sync(~0u, pB1, 2);
        if (tig == 0) {
            int r = wm + mt * 16 + g;
            sq[r    ][2*(w&1)    ] = pA0;
            sq[r    ][2*(w&1) + 1] = pB0;
            sq[r + 8][2*(w&1)    ] = pA1;
            sq[r + 8][2*(w&1) + 1] = pB1;
        }
    }
    __syncthreads();

    const int region = (n0 < 256) ? 0 : (n0 < 512 ? 1 : 2);
    #pragma unroll
    for (int mt = 0; mt < 2; mt++)
        #pragma unroll
        for (int rh = 0; rh < 2; rh++) {
            const int r = wm + mt * 16 + g + rh * 8;
            const int m = m0 + r;
            const int b_ = m >> 11, seq = m & (SEQ - 1);
            float scv = 0.f;
            if (region == 2) {
                float ss = sq[r][0] + sq[r][1] + sq[r][2] + sq[r][3];
                scv = 1.f / fmaxf(sqrtf(ss), 1e-12f);
            }
            #pragma unroll
            for (int nt = 0; nt < 4; nt++) {
                float sc;
                if (region == 2) sc = scv;
                else {
                    int grp = 2 * (w & 1) + (nt >> 1);
                    sc = 1.f / fmaxf(sqrtf(sq[r][grp]), 1e-12f);
                }
                const int n = n0 + wn + nt * 8 + 2 * tig;
                unsigned pv = packh2(Co[mt][nt][2*rh] * sc, Co[mt][nt][2*rh+1] * sc);
                if (region == 0) {
                    int h = n >> 4, d = n & 15;
                    *(unsigned*)&gq[((size_t)(b_*NH + h) * SEQ + seq) * DKH + d] = pv;
                } else if (region == 1) {
                    int j = n - 256, h = j >> 4, d = j & 15;
                    *(unsigned*)&gk[((size_t)(b_*NH + h) * SEQ + seq) * DKH + d] = pv;
                } else {
                    int j = n - 512, h = j >> 6, d = j & 63;
                    *(unsigned*)&gv[((size_t)(b_*NH + h) * SEQ + seq) * DVH + d] = pv;
                }
            }
        }
}

// ---------------- final GEMM: C_f32[MxN] = A @ Bt^T ----------------
__global__ __launch_bounds__(256) void gemm_f16(
    const __half* __restrict__ A, const __half* __restrict__ Bt,
    float* __restrict__ C, int M, int N, int K)
{
    __shared__ unsigned As[3][128][GAS];
    __shared__ unsigned Bs[3][64][GAS];

    const int t = threadIdx.x;
    const int w = t >> 5, lane = t & 31, g = lane >> 2, tig = lane & 3;
    const int wm = (w >> 1) * 32, wn = (w & 1) * 32;
    const int m0 = blockIdx.y * 128, n0 = blockIdx.x * 64;
    const int li = lane & 7, lj = lane >> 3;
    const int ar = t >> 2, ac4 = t & 3;

    const unsigned adrA0 = sptr(&As[0][wm + (lj & 1) * 8 + li][(lj >> 1) * 4]);
    const unsigned adrA1 = adrA0 + 16 * GAS * 4;
    const unsigned adrB  = sptr(&Bs[0][wn + lj * 8 + li][0]);

    CORE_LOAD(A, Bt, K, 0, 0);  CP_COMMIT();
    CORE_LOAD(A, Bt, K, 32, 1); CP_COMMIT();

    float Co[2][4][4] = {};
    const int KT = K / 32;
    for (int kt = 0; kt < KT; kt++) {
        if (kt + 1 < KT) CP_WAIT1(); else CP_WAIT0();
        __syncthreads();
        if (kt + 2 < KT) { CORE_LOAD(A, Bt, K, (kt + 2) * 32, (kt + 2) % 3); CP_COMMIT(); }
        CORE_COMPUTE((unsigned)(kt % 3));
        __syncthreads();
    }

    #pragma unroll
    for (int mt = 0; mt < 2; mt++)
        #pragma unroll
        for (int nt = 0; nt < 4; nt++) {
            int r = m0 + wm + mt * 16 + g;
            int c = n0 + wn + nt * 8 + 2 * tig;
            *(float2*)&C[(size_t)r * N + c]       = make_float2(Co[mt][nt][0], Co[mt][nt][1]);
            *(float2*)&C[(size_t)(r + 8) * N + c] = make_float2(Co[mt][nt][2], Co[mt][nt][3]);
        }
}

// ---------------- fused attention: register-resident S (R5-proven) --------
#define AQS  12
#define AVSH 72
__global__ __launch_bounds__(256) void attn_f16(
    const __half* __restrict__ gq, const __half* __restrict__ gk,
    const __half* __restrict__ gv, __half* __restrict__ gao)
{
    __shared__ unsigned Qs[128][AQS];
    __shared__ unsigned Ks[2][64][AQS];
    __shared__ __half   Vs[2][64][AVSH];

    const int t = threadIdx.x;
    const int w = t >> 5, lane = t & 31, g = lane >> 2, tig = lane & 3;
    const int wm = w * 16;
    const int bh = blockIdx.y, q0 = blockIdx.x * 128;
    const int li = lane & 7, lj = lane >> 3;

    const __half* qb = gq + (size_t)bh * SEQ * DKH;
    const __half* kb = gk + (size_t)bh * SEQ * DKH;
    const __half* vb = gv + (size_t)bh * SEQ * DVH;

    {
        int r = t >> 1, hf = t & 1;
        *(uint4*)&Qs[r][hf * 4] = *(const uint4*)&qb[(size_t)(q0 + r) * DKH + hf * 8];
    }

    const int kr = t >> 1, khf = t & 1;
    const int vr = t >> 3, vc = (t & 7) * 8;
    #define ATTN_LOAD(k0_, buf_) do {                                            \
        if (t < 128)                                                             \
            cpa16(sptr(&Ks[buf_][kr][khf*4]), &kb[(size_t)((k0_)+kr)*DKH + khf*8]); \
        cpa16(sptr(&Vs[buf_][vr][vc]),      &vb[(size_t)((k0_)+vr)*DVH + vc]);   \
        cpa16(sptr(&Vs[buf_][vr+32][vc]),   &vb[(size_t)((k0_)+vr+32)*DVH + vc]);\
    } while(0)

    ATTN_LOAD(0, 0);
    CP_COMMIT();
    __syncthreads();

    unsigned aq[4];
    ldm4(aq, sptr(&Qs[wm + (lj & 1) * 8 + li][(lj >> 1) * 4]));

    const unsigned KBUF = 64 * AQS * 4, VBUF = 64 * AVSH * 2;
    const unsigned adrK = sptr(&Ks[0][lj * 8 + li][0]);
    const unsigned adrV = sptr(&Vs[0][(lj & 1) * 8 + li][(lj >> 1) * 8]);

    float Co[8][4] = {};

    const int NT = SEQ / 64;
    for (int kt = 0; kt < NT; kt++) {
        CP_WAIT0();
        __syncthreads();
        if (kt + 1 < NT) { ATTN_LOAD((kt + 1) * 64, (kt + 1) & 1); CP_COMMIT(); }
        const unsigned kbase = adrK + (kt & 1) * KBUF;
        const unsigned vbase = adrV + (kt & 1) * VBUF;

        float Cs[8][4] = {};
        {
            unsigned b0[4], b1[4], b2[4], b3[4];
            ldm4(b0, kbase);
            ldm4(b1, kbase + 16);
            ldm4(b2, kbase + 32 * AQS * 4);
            ldm4(b3, kbase + 32 * AQS * 4 + 16);
            #pragma unroll
            for (int nt = 0; nt < 4; nt++) {
                unsigned bA[2] = { b0[nt], b1[nt] };
                unsigned bB[2] = { b2[nt], b3[nt] };
                mma16(Cs[nt],     aq, bA);
                mma16(Cs[4 + nt], aq, bB);
            }
        }

        unsigned sf[4][4];
        #pragma unroll
        for (int ks = 0; ks < 4; ks++) {
            float r0 = Cs[2*ks][0];   r0 = r0 > 0.f ? r0*r0 : 0.f;
            float r1 = Cs[2*ks][1];   r1 = r1 > 0.f ? r1*r1 : 0.f;
            float r2 = Cs[2*ks][2];   r2 = r2 > 0.f ? r2*r2 : 0.f;
            float r3 = Cs[2*ks][3];   r3 = r3 > 0.f ? r3*r3 : 0.f;
            float r4 = Cs[2*ks+1][0]; r4 = r4 > 0.f ? r4*r4 : 0.f;
            float r5 = Cs[2*ks+1][1]; r5 = r5 > 0.f ? r5*r5 : 0.f;
            float r6 = Cs[2*ks+1][2]; r6 = r6 > 0.f ? r6*r6 : 0.f;
            float r7 = Cs[2*ks+1][3]; r7 = r7 > 0.f ? r7*r7 : 0.f;
            sf[ks][0] = packh2(r0, r1);
            sf[ks][1] = packh2(r2, r3);
            sf[ks][2] = packh2(r4, r5);
            sf[ks][3] = packh2(r6, r7);
        }

        #pragma unroll
        for (int ks = 0; ks < 4; ks++) {
            const unsigned vk = vbase + ks * 16 * AVSH * 2;
            #pragma unroll
            for (int j = 0; j < 4; j++) {
                unsigned vv[4];
                ldm4t(vv, vk + j * 32);
                unsigned bA[2] = { vv[0], vv[1] };
                unsigned bB[2] = { vv[2], vv[3] };
                mma16(Co[2*j],     sf[ks], bA);
                mma16(Co[2*j + 1], sf[ks], bB);
            }
        }
        __syncthreads();
    }

    float s0 = 0.f, s1 = 0.f;
    #pragma unroll
    for (int nt = 0; nt < 8; nt++) {
        s0 += Co[nt][0]*Co[nt][0] + Co[nt][1]*Co[nt][1];
        s1 += Co[nt][2]*Co[nt][2] + Co[nt][3]*Co[nt][3];
    }
    s0 += __shfl_xor_sync(~0u, s0, 1); s0 += __shfl_xor_sync(~0u, s0, 2);
    s1 += __shfl_xor_sync(~0u, s1, 1); s1 += __shfl_xor_sync(~0u, s1, 2);
    float n0s = sqrtf(s0), n1s = sqrtf(s1);
    float sc0 = tanhf(n0s) / fmaxf(n0s, 1e-12f);
    float sc1 = tanhf(n1s) / fmaxf(n1s, 1e-12f);

    const int b_ = bh >> 4, h_ = bh & 15;
    const int row0 = q0 + wm + g, row1 = row0 + 8;
    __half* d0 = gao + (size_t)(b_ * SEQ + row0) * OCOLS + h_ * DVH;
    __half* d1 = gao + (size_t)(b_ * SEQ + row1) * OCOLS + h_ * DVH;
    #pragma unroll
    for (int nt = 0; nt < 8; nt++) {
        int c = nt * 8 + 2 * tig;
        *(unsigned*)&d0[c] = packh2(Co[nt][0] * sc0, Co[nt][1] * sc0);
        *(unsigned*)&d1[c] = packh2(Co[nt][2] * sc1, Co[nt][3] * sc1);
    }
}

// ---------------- host launch ----------------
extern "C" void kernel_launch(void* const* d_in, const int* in_sizes, int n_in,
                              void* d_out, int out_size)
{
    const float *tokens = nullptr, *Wq = nullptr, *Wkv = nullptr, *Wout = nullptr;
    for (int i = 0; i < n_in; i++) {
        switch (in_sizes[i]) {
            case NTOK * DIM:   tokens = (const float*)d_in[i]; break;
            case DIM * QCOLS:  Wq     = (const float*)d_in[i]; break;
            case DIM * KVCOLS: Wkv    = (const float*)d_in[i]; break;
            case OCOLS * DIM:  Wout   = (const float*)d_in[i]; break;
        }
    }

    __half *tokh, *wc, *wot, *qn, *kn, *vh, *aoh;
    cudaGetSymbolAddress((void**)&tokh, g_tokh);
    cudaGetSymbolAddress((void**)&wc,   g_wc);
    cudaGetSymbolAddress((void**)&wot,  g_wot);
    cudaGetSymbolAddress((void**)&qn,   g_qn);
    cudaGetSymbolAddress((void**)&kn,   g_kn);
    cudaGetSymbolAddress((void**)&vh,   g_vh);
    cudaGetSymbolAddress((void**)&aoh,  g_aoh);

    cvt_f2h<<<(NTOK*DIM/8 + 255)/256, 256>>>(tokens, tokh, NTOK*DIM/8);
    wprep<<<dim3(PCOLS/32, DIM/32), 256>>>(Wq, Wkv, wc);
    wtrans<<<dim3(DIM/32, OCOLS/32), 256>>>(Wout, wot, DIM, OCOLS);

    proj_gemm<<<dim3(PCOLS/64, NTOK/128), 256>>>(tokh, wc, qn, kn, vh);

    attn_f16<<<dim3(SEQ/128, BATCH*NH), 256>>>(qn, kn, vh, aoh);

    gemm_f16<<<dim3(DIM/64, NTOK/128), 256>>>(aoh, wot, (float*)d_out, NTOK, DIM, OCOLS);
}

// round 10
// speedup vs baseline: 1.0233x; 1.0233x over previous
#include <cuda_runtime.h>
#include <cuda_fp16.h>
#include <cmath>

// Problem constants
#define BATCH   2
#define SEQ     2048
#define DIM     1024
#define NH      16
#define DKH     16
#define DVH     64
#define NTOK    (BATCH*SEQ)          // 4096
#define QCOLS   (NH*DKH)             // 256
#define KVCOLS  (NH*(DKH+DVH))       // 1280
#define OCOLS   (NH*DVH)             // 1024
#define PCOLS   1536                 // 256 q + 256 k + 1024 v (permuted)

// ---------------- scratch ----------------
__device__ __half g_tokh[NTOK * DIM];
__device__ __half g_wc  [PCOLS * DIM];
__device__ __half g_wot [DIM * OCOLS];
__device__ __half g_qn[BATCH*NH*SEQ*DKH];
__device__ __half g_kn[BATCH*NH*SEQ*DKH];
__device__ __half g_vh[BATCH*NH*SEQ*DVH];
__device__ __half g_aoh[NTOK * OCOLS];

// ---------------- helpers ----------------
__device__ __forceinline__ unsigned packh2(float a, float b){
    __half2 h = __floats2half2_rn(a, b);
    return *(unsigned*)&h;
}
__device__ __forceinline__ unsigned sptr(const void* p){
    return (unsigned)__cvta_generic_to_shared(p);
}
__device__ __forceinline__ void ldm4(unsigned r[4], unsigned a){
    asm volatile("ldmatrix.sync.aligned.m8n8.x4.shared.b16 {%0,%1,%2,%3}, [%4];"
        : "=r"(r[0]),"=r"(r[1]),"=r"(r[2]),"=r"(r[3]) : "r"(a));
}
__device__ __forceinline__ void ldm4t(unsigned r[4], unsigned a){
    asm volatile("ldmatrix.sync.aligned.m8n8.x4.trans.shared.b16 {%0,%1,%2,%3}, [%4];"
        : "=r"(r[0]),"=r"(r[1]),"=r"(r[2]),"=r"(r[3]) : "r"(a));
}
__device__ __forceinline__ void mma16(float* c, const unsigned* a, const unsigned* b){
    asm volatile("mma.sync.aligned.m16n8k16.row.col.f32.f16.f16.f32 "
        "{%0,%1,%2,%3},{%4,%5,%6,%7},{%8,%9},{%0,%1,%2,%3};\n"
        : "+f"(c[0]),"+f"(c[1]),"+f"(c[2]),"+f"(c[3])
        : "r"(a[0]),"r"(a[1]),"r"(a[2]),"r"(a[3]),"r"(b[0]),"r"(b[1]));
}
__device__ __forceinline__ void cpa16(unsigned dst, const void* src){
    asm volatile("cp.async.cg.shared.global [%0], [%1], 16;" :: "r"(dst), "l"(src));
}
#define CP_COMMIT() asm volatile("cp.async.commit_group;" ::: "memory")
#define CP_WAIT0()  asm volatile("cp.async.wait_group 0;" ::: "memory")
#define CP_WAIT1()  asm volatile("cp.async.wait_group 1;" ::: "memory")
#define CP_WAIT2()  asm volatile("cp.async.wait_group 2;" ::: "memory")

// ---------------- prep kernels ----------------
__global__ __launch_bounds__(256) void cvt_f2h(const float* __restrict__ src,
                                              __half* __restrict__ dst, int n8)
{
    int i = blockIdx.x * blockDim.x + threadIdx.x;
    if (i >= n8) return;
    float4 a = ((const float4*)src)[2*i];
    float4 b = ((const float4*)src)[2*i+1];
    uint4 p = make_uint4(packh2(a.x,a.y), packh2(a.z,a.w),
                         packh2(b.x,b.y), packh2(b.z,b.w));
    ((uint4*)dst)[i] = p;
}

__global__ __launch_bounds__(256) void wprep(const float* __restrict__ Wq,
                                             const float* __restrict__ Wkv,
                                             __half* __restrict__ Wc)
{
    __shared__ float ts[32][33];
    const int n0 = blockIdx.x * 32, k0 = blockIdx.y * 32;
    const int tx = threadIdx.x & 31, ty = threadIdx.x >> 5;
    {
        const int n = n0 + tx;
        const float* W; int c, ld;
        if (n < 256)      { W = Wq;  ld = QCOLS;  c = n; }
        else if (n < 512) { int j = n - 256; W = Wkv; ld = KVCOLS; c = (j >> 4) * 80 + (j & 15); }
        else              { int j = n - 512; W = Wkv; ld = KVCOLS; c = (j >> 6) * 80 + 16 + (j & 63); }
        #pragma unroll
        for (int i = 0; i < 32; i += 8)
            ts[ty + i][tx] = W[(size_t)(k0 + ty + i) * ld + c];
    }
    __syncthreads();
    #pragma unroll
    for (int i = 0; i < 32; i += 8)
        Wc[(size_t)(n0 + ty + i) * DIM + k0 + tx] = __float2half(ts[tx][ty + i]);
}

__global__ __launch_bounds__(256) void wtrans(const float* __restrict__ W,
                                              __half* __restrict__ Wt, int N, int K)
{
    __shared__ float ts[32][33];
    const int n0 = blockIdx.x * 32, k0 = blockIdx.y * 32;
    const int tx = threadIdx.x & 31, ty = threadIdx.x >> 5;
    #pragma unroll
    for (int i = 0; i < 32; i += 8)
        ts[ty + i][tx] = W[(size_t)(k0 + ty + i) * N + n0 + tx];
    __syncthreads();
    #pragma unroll
    for (int i = 0; i < 32; i += 8)
        Wt[(size_t)(n0 + ty + i) * K + k0 + tx] = __float2half(ts[tx][ty + i]);
}

// ====== GEMM core: 128x64 block, 8 warps, warp 32x32 ======
// 4-stage cp.async ring (&3 indexing), ONE sync per iter, K fixed = 1024.
#define GAS  20
#define ASTG (128 * GAS * 4)     // 10240 B per A stage
#define BSTG (64 * GAS * 4)      // 5120 B per B stage
#define SMEM_GEMM (4 * (ASTG + BSTG))   // 61440 B

// A stages at [0, 4*ASTG), B stages at [4*ASTG, ...)
#define CORE_LOAD(AP, BP, k0_, st_) do {                                          \
    cpa16(asb + (st_)*ASTG + ar*80 + ac4*16,                                      \
          &(AP)[(size_t)(m0+ar)*1024 + (k0_) + ac4*8]);                           \
    cpa16(asb + (st_)*ASTG + (ar+64)*80 + ac4*16,                                 \
          &(AP)[(size_t)(m0+ar+64)*1024 + (k0_) + ac4*8]);                        \
    cpa16(bsb + (st_)*BSTG + ar*80 + ac4*16,                                      \
          &(BP)[(size_t)(n0+ar)*1024 + (k0_) + ac4*8]);                           \
} while(0)

#define CORE_COMPUTE(st_) do {                                                    \
    const unsigned oa = (st_) * (unsigned)ASTG;                                   \
    const unsigned ob = (st_) * (unsigned)BSTG;                                   \
    _Pragma("unroll")                                                             \
    for (int ks = 0; ks < 2; ks++) {                                              \
        const unsigned cb = ks * 32;                                              \
        unsigned a0[4], a1[4], b0[4], b1[4];                                      \
        ldm4(a0, adrA0 + oa + cb);                                                \
        ldm4(a1, adrA1 + oa + cb);                                                \
        ldm4(b0, adrB + ob + cb);                                                 \
        ldm4(b1, adrB + ob + cb + 16);                                            \
        _Pragma("unroll")                                                         \
        for (int nt = 0; nt < 4; nt++) {                                          \
            unsigned bb[2] = { b0[nt], b1[nt] };                                  \
            mma16(Co[0][nt], a0, bb);                                             \
            mma16(Co[1][nt], a1, bb);                                             \
        }                                                                         \
    }                                                                             \
} while(0)

#define CORE_MAINLOOP(AP, BP)                                                     \
    CORE_LOAD(AP, BP, 0,  0); CP_COMMIT();                                        \
    CORE_LOAD(AP, BP, 32, 1); CP_COMMIT();                                        \
    CORE_LOAD(AP, BP, 64, 2); CP_COMMIT();                                        \
    _Pragma("unroll 4")                                                           \
    for (int kt = 0; kt < 32; kt++) {                                             \
        if (kt < 30) CP_WAIT2(); else if (kt < 31) CP_WAIT1(); else CP_WAIT0();   \
        __syncthreads();                                                          \
        if (kt + 3 < 32) { CORE_LOAD(AP, BP, (kt + 3) * 32, (kt + 3) & 3); CP_COMMIT(); } \
        CORE_COMPUTE(kt & 3);                                                     \
    }

// ---------------- fused projection GEMM + l2norm + head scatter ------------
__global__ __launch_bounds__(256) void proj_gemm(
    const __half* __restrict__ A, const __half* __restrict__ Bt,
    __half* __restrict__ gq, __half* __restrict__ gk, __half* __restrict__ gv)
{
    extern __shared__ unsigned char dynsmem[];
    __shared__ float sq[128][4];

    const int t = threadIdx.x;
    const int w = t >> 5, lane = t & 31, g = lane >> 2, tig = lane & 3;
    const int wm = (w >> 1) * 32, wn = (w & 1) * 32;
    const int m0 = blockIdx.y * 128, n0 = blockIdx.x * 64;
    const int li = lane & 7, lj = lane >> 3;
    const int ar = t >> 2, ac4 = t & 3;

    const unsigned asb = sptr(dynsmem);
    const unsigned bsb = asb + 4 * ASTG;
    const unsigned adrA0 = asb + (wm + (lj & 1) * 8 + li) * 80 + (lj >> 1) * 16;
    const unsigned adrA1 = adrA0 + 16 * 80;
    const unsigned adrB  = bsb + (wn + lj * 8 + li) * 80;

    float Co[2][4][4] = {};
    CORE_MAINLOOP(A, Bt)
    __syncthreads();

    // ---- epilogue: group sums of squares (R5-proven) ----
    #pragma unroll
    for (int mt = 0; mt < 2; mt++) {
        float pA0 = 0, pA1 = 0, pB0 = 0, pB1 = 0;
        #pragma unroll
        for (int nt = 0; nt < 2; nt++) {
            pA0 += Co[mt][nt][0]*Co[mt][nt][0] + Co[mt][nt][1]*Co[mt][nt][1];
            pA1 += Co[mt][nt][2]*Co[mt][nt][2] + Co[mt][nt][3]*Co[mt][nt][3];
            pB0 += Co[mt][nt+2][0]*Co[mt][nt+2][0] + Co[mt][nt+2][1]*Co[mt][nt+2][1];
            pB1 += Co[mt][nt+2][2]*Co[mt][nt+2][2] + Co[mt][nt+2][3]*Co[mt][nt+2][3];
        }
        pA0 += __shfl_xor_sync(~0u, pA0, 1); pA0 += __shfl_xor_sync(~0u, pA0, 2);
        pA1 += __shfl_xor_sync(~0u, pA1, 1); pA1 += __shfl_xor_sync(~0u, pA1, 2);
        pB0 += __shfl_xor_sync(~0u, pB0, 1); pB0 += __shfl_xor_sync(~0u, pB0, 2);
        pB1 += __shfl_xor_sync(~0u, pB1, 1); pB1 += __shfl_xor_sync(~0u, pB1, 2);
        if (tig == 0) {
            int r = wm + mt * 16 + g;
            sq[r    ][2*(w&1)    ] = pA0;
            sq[r    ][2*(w&1) + 1] = pB0;
            sq[r + 8][2*(w&1)    ] = pA1;
            sq[r + 8][2*(w&1) + 1] = pB1;
        }
    }
    __syncthreads();

    const int region = (n0 < 256) ? 0 : (n0 < 512 ? 1 : 2);
    #pragma unroll
    for (int mt = 0; mt < 2; mt++)
        #pragma unroll
        for (int rh = 0; rh < 2; rh++) {
            const int r = wm + mt * 16 + g + rh * 8;
            const int m = m0 + r;
            const int b_ = m >> 11, seq = m & (SEQ - 1);
            float scv = 0.f;
            if (region == 2) {
                float ss = sq[r][0] + sq[r][1] + sq[r][2] + sq[r][3];
                scv = 1.f / fmaxf(sqrtf(ss), 1e-12f);
            }
            #pragma unroll
            for (int nt = 0; nt < 4; nt++) {
                float sc;
                if (region == 2) sc = scv;
                else {
                    int grp = 2 * (w & 1) + (nt >> 1);
                    sc = 1.f / fmaxf(sqrtf(sq[r][grp]), 1e-12f);
                }
                const int n = n0 + wn + nt * 8 + 2 * tig;
                unsigned pv = packh2(Co[mt][nt][2*rh] * sc, Co[mt][nt][2*rh+1] * sc);
                if (region == 0) {
                    int h = n >> 4, d = n & 15;
                    *(unsigned*)&gq[((size_t)(b_*NH + h) * SEQ + seq) * DKH + d] = pv;
                } else if (region == 1) {
                    int j = n - 256, h = j >> 4, d = j & 15;
                    *(unsigned*)&gk[((size_t)(b_*NH + h) * SEQ + seq) * DKH + d] = pv;
                } else {
                    int j = n - 512, h = j >> 6, d = j & 63;
                    *(unsigned*)&gv[((size_t)(b_*NH + h) * SEQ + seq) * DVH + d] = pv;
                }
            }
        }
}

// ---------------- final GEMM: C_f32[4096x1024] = A @ Bt^T (K=1024) ---------
__global__ __launch_bounds__(256) void gemm_f16(
    const __half* __restrict__ A, const __half* __restrict__ Bt,
    float* __restrict__ C)
{
    extern __shared__ unsigned char dynsmem[];

    const int t = threadIdx.x;
    const int w = t >> 5, lane = t & 31, g = lane >> 2, tig = lane & 3;
    const int wm = (w >> 1) * 32, wn = (w & 1) * 32;
    const int m0 = blockIdx.y * 128, n0 = blockIdx.x * 64;
    const int li = lane & 7, lj = lane >> 3;
    const int ar = t >> 2, ac4 = t & 3;

    const unsigned asb = sptr(dynsmem);
    const unsigned bsb = asb + 4 * ASTG;
    const unsigned adrA0 = asb + (wm + (lj & 1) * 8 + li) * 80 + (lj >> 1) * 16;
    const unsigned adrA1 = adrA0 + 16 * 80;
    const unsigned adrB  = bsb + (wn + lj * 8 + li) * 80;

    float Co[2][4][4] = {};
    CORE_MAINLOOP(A, Bt)

    #pragma unroll
    for (int mt = 0; mt < 2; mt++)
        #pragma unroll
        for (int nt = 0; nt < 4; nt++) {
            int r = m0 + wm + mt * 16 + g;
            int c = n0 + wn + nt * 8 + 2 * tig;
            *(float2*)&C[(size_t)r * DIM + c]       = make_float2(Co[mt][nt][0], Co[mt][nt][1]);
            *(float2*)&C[(size_t)(r + 8) * DIM + c] = make_float2(Co[mt][nt][2], Co[mt][nt][3]);
        }
}

// ---------------- fused attention: register-resident S (R5-proven) --------
#define AQS  12
#define AVSH 72
__global__ __launch_bounds__(256) void attn_f16(
    const __half* __restrict__ gq, const __half* __restrict__ gk,
    const __half* __restrict__ gv, __half* __restrict__ gao)
{
    __shared__ unsigned Qs[128][AQS];
    __shared__ unsigned Ks[2][64][AQS];
    __shared__ __half   Vs[2][64][AVSH];

    const int t = threadIdx.x;
    const int w = t >> 5, lane = t & 31, g = lane >> 2, tig = lane & 3;
    const int wm = w * 16;
    const int bh = blockIdx.y, q0 = blockIdx.x * 128;
    const int li = lane & 7, lj = lane >> 3;

    const __half* qb = gq + (size_t)bh * SEQ * DKH;
    const __half* kb = gk + (size_t)bh * SEQ * DKH;
    const __half* vb = gv + (size_t)bh * SEQ * DVH;

    {
        int r = t >> 1, hf = t & 1;
        *(uint4*)&Qs[r][hf * 4] = *(const uint4*)&qb[(size_t)(q0 + r) * DKH + hf * 8];
    }

    const int kr = t >> 1, khf = t & 1;
    const int vr = t >> 3, vc = (t & 7) * 8;
    #define ATTN_LOAD(k0_, buf_) do {                                            \
        if (t < 128)                                                             \
            cpa16(sptr(&Ks[buf_][kr][khf*4]), &kb[(size_t)((k0_)+kr)*DKH + khf*8]); \
        cpa16(sptr(&Vs[buf_][vr][vc]),      &vb[(size_t)((k0_)+vr)*DVH + vc]);   \
        cpa16(sptr(&Vs[buf_][vr+32][vc]),   &vb[(size_t)((k0_)+vr+32)*DVH + vc]);\
    } while(0)

    ATTN_LOAD(0, 0);
    CP_COMMIT();
    __syncthreads();

    unsigned aq[4];
    ldm4(aq, sptr(&Qs[wm + (lj & 1) * 8 + li][(lj >> 1) * 4]));

    const unsigned KBUF = 64 * AQS * 4, VBUF = 64 * AVSH * 2;
    const unsigned adrK = sptr(&Ks[0][lj * 8 + li][0]);
    const unsigned adrV = sptr(&Vs[0][(lj & 1) * 8 + li][(lj >> 1) * 8]);

    float Co[8][4] = {};

    const int NT = SEQ / 64;
    for (int kt = 0; kt < NT; kt++) {
        CP_WAIT0();
        __syncthreads();
        if (kt + 1 < NT) { ATTN_LOAD((kt + 1) * 64, (kt + 1) & 1); CP_COMMIT(); }
        const unsigned kbase = adrK + (kt & 1) * KBUF;
        const unsigned vbase = adrV + (kt & 1) * VBUF;

        float Cs[8][4] = {};
        {
            unsigned b0[4], b1[4], b2[4], b3[4];
            ldm4(b0, kbase);
            ldm4(b1, kbase + 16);
            ldm4(b2, kbase + 32 * AQS * 4);
            ldm4(b3, kbase + 32 * AQS * 4 + 16);
            #pragma unroll
            for (int nt = 0; nt < 4; nt++) {
                unsigned bA[2] = { b0[nt], b1[nt] };
                unsigned bB[2] = { b2[nt], b3[nt] };
                mma16(Cs[nt],     aq, bA);
                mma16(Cs[4 + nt], aq, bB);
            }
        }

        unsigned sf[4][4];
        #pragma unroll
        for (int ks = 0; ks < 4; ks++) {
            float r0 = Cs[2*ks][0];   r0 = r0 > 0.f ? r0*r0 : 0.f;
            float r1 = Cs[2*ks][1];   r1 = r1 > 0.f ? r1*r1 : 0.f;
            float r2 = Cs[2*ks][2];   r2 = r2 > 0.f ? r2*r2 : 0.f;
            float r3 = Cs[2*ks][3];   r3 = r3 > 0.f ? r3*r3 : 0.f;
            float r4 = Cs[2*ks+1][0]; r4 = r4 > 0.f ? r4*r4 : 0.f;
            float r5 = Cs[2*ks+1][1]; r5 = r5 > 0.f ? r5*r5 : 0.f;
            float r6 = Cs[2*ks+1][2]; r6 = r6 > 0.f ? r6*r6 : 0.f;
            float r7 = Cs[2*ks+1][3]; r7 = r7 > 0.f ? r7*r7 : 0.f;
            sf[ks][0] = packh2(r0, r1);
            sf[ks][1] = packh2(r2, r3);
            sf[ks][2] = packh2(r4, r5);
            sf[ks][3] = packh2(r6, r7);
        }

        #pragma unroll
        for (int ks = 0; ks < 4; ks++) {
            const unsigned vk = vbase + ks * 16 * AVSH * 2;
            #pragma unroll
            for (int j = 0; j < 4; j++) {
                unsigned vv[4];
                ldm4t(vv, vk + j * 32);
                unsigned bA[2] = { vv[0], vv[1] };
                unsigned bB[2] = { vv[2], vv[3] };
                mma16(Co[2*j],     sf[ks], bA);
                mma16(Co[2*j + 1], sf[ks], bB);
            }
        }
        __syncthreads();
    }

    float s0 = 0.f, s1 = 0.f;
    #pragma unroll
    for (int nt = 0; nt < 8; nt++) {
        s0 += Co[nt][0]*Co[nt][0] + Co[nt][1]*Co[nt][1];
        s1 += Co[nt][2]*Co[nt][2] + Co[nt][3]*Co[nt][3];
    }
    s0 += __shfl_xor_sync(~0u, s0, 1); s0 += __shfl_xor_sync(~0u, s0, 2);
    s1 += __shfl_xor_sync(~0u, s1, 1); s1 += __shfl_xor_sync(~0u, s1, 2);
    float n0s = sqrtf(s0), n1s = sqrtf(s1);
    float sc0 = tanhf(n0s) / fmaxf(n0s, 1e-12f);
    float sc1 = tanhf(n1s) / fmaxf(n1s, 1e-12f);

    const int b_ = bh >> 4, h_ = bh & 15;
    const int row0 = q0 + wm + g, row1 = row0 + 8;
    __half* d0 = gao + (size_t)(b_ * SEQ + row0) * OCOLS + h_ * DVH;
    __half* d1 = gao + (size_t)(b_ * SEQ + row1) * OCOLS + h_ * DVH;
    #pragma unroll
    for (int nt = 0; nt < 8; nt++) {
        int c = nt * 8 + 2 * tig;
        *(unsigned*)&d0[c] = packh2(Co[nt][0] * sc0, Co[nt][1] * sc0);
        *(unsigned*)&d1[c] = packh2(Co[nt][2] * sc1, Co[nt][3] * sc1);
    }
}

// ---------------- host launch ----------------
extern "C" void kernel_launch(void* const* d_in, const int* in_sizes, int n_in,
                              void* d_out, int out_size)
{
    const float *tokens = nullptr, *Wq = nullptr, *Wkv = nullptr, *Wout = nullptr;
    for (int i = 0; i < n_in; i++) {
        switch (in_sizes[i]) {
            case NTOK * DIM:   tokens = (const float*)d_in[i]; break;
            case DIM * QCOLS:  Wq     = (const float*)d_in[i]; break;
            case DIM * KVCOLS: Wkv    = (const float*)d_in[i]; break;
            case OCOLS * DIM:  Wout   = (const float*)d_in[i]; break;
        }
    }

    __half *tokh, *wc, *wot, *qn, *kn, *vh, *aoh;
    cudaGetSymbolAddress((void**)&tokh, g_tokh);
    cudaGetSymbolAddress((void**)&wc,   g_wc);
    cudaGetSymbolAddress((void**)&wot,  g_wot);
    cudaGetSymbolAddress((void**)&qn,   g_qn);
    cudaGetSymbolAddress((void**)&kn,   g_kn);
    cudaGetSymbolAddress((void**)&vh,   g_vh);
    cudaGetSymbolAddress((void**)&aoh,  g_aoh);

    cudaFuncSetAttribute(proj_gemm, cudaFuncAttributeMaxDynamicSharedMemorySize, SMEM_GEMM);
    cudaFuncSetAttribute(gemm_f16,  cudaFuncAttributeMaxDynamicSharedMemorySize, SMEM_GEMM);

    cvt_f2h<<<(NTOK*DIM/8 + 255)/256, 256>>>(tokens, tokh, NTOK*DIM/8);
    wprep<<<dim3(PCOLS/32, DIM/32), 256>>>(Wq, Wkv, wc);
    wtrans<<<dim3(DIM/32, OCOLS/32), 256>>>(Wout, wot, DIM, OCOLS);

    proj_gemm<<<dim3(PCOLS/64, NTOK/128), 256, SMEM_GEMM>>>(tokh, wc, qn, kn, vh);

    attn_f16<<<dim3(SEQ/128, BATCH*NH), 256>>>(qn, kn, vh, aoh);

    gemm_f16<<<dim3(DIM/64, NTOK/128), 256, SMEM_GEMM>>>(aoh, wot, (float*)d_out);
}

// round 11
// speedup vs baseline: 1.0782x; 1.0536x over previous
#include <cuda_runtime.h>
#include <cuda_fp16.h>
#include <cmath>

// Problem constants
#define BATCH   2
#define SEQ     2048
#define DIM     1024
#define NH      16
#define DKH     16
#define DVH     64
#define NTOK    (BATCH*SEQ)          // 4096
#define QCOLS   (NH*DKH)             // 256
#define KVCOLS  (NH*(DKH+DVH))       // 1280
#define OCOLS   (NH*DVH)             // 1024
#define PCOLS   1536                 // 256 q + 256 k + 1024 v (permuted)

// ---------------- scratch ----------------
__device__ __half g_tokh[NTOK * DIM];
__device__ __half g_wc  [PCOLS * DIM];
__device__ __half g_wot [DIM * OCOLS];
__device__ __half g_qn[BATCH*NH*SEQ*DKH];
__device__ __half g_kn[BATCH*NH*SEQ*DKH];
__device__ __half g_vh[BATCH*NH*SEQ*DVH];
__device__ __half g_aoh[NTOK * OCOLS];

// ---------------- helpers ----------------
__device__ __forceinline__ unsigned packh2(float a, float b){
    __half2 h = __floats2half2_rn(a, b);
    return *(unsigned*)&h;
}
__device__ __forceinline__ unsigned sptr(const void* p){
    return (unsigned)__cvta_generic_to_shared(p);
}
__device__ __forceinline__ void ldm4(unsigned r[4], unsigned a){
    asm volatile("ldmatrix.sync.aligned.m8n8.x4.shared.b16 {%0,%1,%2,%3}, [%4];"
        : "=r"(r[0]),"=r"(r[1]),"=r"(r[2]),"=r"(r[3]) : "r"(a));
}
__device__ __forceinline__ void ldm4t(unsigned r[4], unsigned a){
    asm volatile("ldmatrix.sync.aligned.m8n8.x4.trans.shared.b16 {%0,%1,%2,%3}, [%4];"
        : "=r"(r[0]),"=r"(r[1]),"=r"(r[2]),"=r"(r[3]) : "r"(a));
}
__device__ __forceinline__ void mma16(float* c, const unsigned* a, const unsigned* b){
    asm volatile("mma.sync.aligned.m16n8k16.row.col.f32.f16.f16.f32 "
        "{%0,%1,%2,%3},{%4,%5,%6,%7},{%8,%9},{%0,%1,%2,%3};\n"
        : "+f"(c[0]),"+f"(c[1]),"+f"(c[2]),"+f"(c[3])
        : "r"(a[0]),"r"(a[1]),"r"(a[2]),"r"(a[3]),"r"(b[0]),"r"(b[1]));
}
__device__ __forceinline__ void cpa16(unsigned dst, const void* src){
    asm volatile("cp.async.cg.shared.global [%0], [%1], 16;" :: "r"(dst), "l"(src));
}
#define CP_COMMIT() asm volatile("cp.async.commit_group;" ::: "memory")
#define CP_WAIT0()  asm volatile("cp.async.wait_group 0;" ::: "memory")

// ---------------- prep kernels ----------------
__global__ __launch_bounds__(256) void cvt_f2h(const float* __restrict__ src,
                                              __half* __restrict__ dst, int n8)
{
    int i = blockIdx.x * blockDim.x + threadIdx.x;
    if (i >= n8) return;
    float4 a = ((const float4*)src)[2*i];
    float4 b = ((const float4*)src)[2*i+1];
    uint4 p = make_uint4(packh2(a.x,a.y), packh2(a.z,a.w),
                         packh2(b.x,b.y), packh2(b.z,b.w));
    ((uint4*)dst)[i] = p;
}

__global__ __launch_bounds__(256) void wprep(const float* __restrict__ Wq,
                                             const float* __restrict__ Wkv,
                                             __half* __restrict__ Wc)
{
    __shared__ float ts[32][33];
    const int n0 = blockIdx.x * 32, k0 = blockIdx.y * 32;
    const int tx = threadIdx.x & 31, ty = threadIdx.x >> 5;
    {
        const int n = n0 + tx;
        const float* W; int c, ld;
        if (n < 256)      { W = Wq;  ld = QCOLS;  c = n; }
        else if (n < 512) { int j = n - 256; W = Wkv; ld = KVCOLS; c = (j >> 4) * 80 + (j & 15); }
        else              { int j = n - 512; W = Wkv; ld = KVCOLS; c = (j >> 6) * 80 + 16 + (j & 63); }
        #pragma unroll
        for (int i = 0; i < 32; i += 8)
            ts[ty + i][tx] = W[(size_t)(k0 + ty + i) * ld + c];
    }
    __syncthreads();
    #pragma unroll
    for (int i = 0; i < 32; i += 8)
        Wc[(size_t)(n0 + ty + i) * DIM + k0 + tx] = __float2half(ts[tx][ty + i]);
}

__global__ __launch_bounds__(256) void wtrans(const float* __restrict__ W,
                                              __half* __restrict__ Wt, int N, int K)
{
    __shared__ float ts[32][33];
    const int n0 = blockIdx.x * 32, k0 = blockIdx.y * 32;
    const int tx = threadIdx.x & 31, ty = threadIdx.x >> 5;
    #pragma unroll
    for (int i = 0; i < 32; i += 8)
        ts[ty + i][tx] = W[(size_t)(k0 + ty + i) * N + n0 + tx];
    __syncthreads();
    #pragma unroll
    for (int i = 0; i < 32; i += 8)
        Wt[(size_t)(n0 + ty + i) * K + k0 + tx] = __float2half(ts[tx][ty + i]);
}

// ====== GEMM core: 128x64 block, 8 warps, warp 32x32, BK=64, 2 stages =====
// Row = 64 halfs (128B data) + 16B pad = 144B stride. 32 MMA per warp/barrier.
#define RSTRIDE 144
#define ASTG (128 * RSTRIDE)            // 18432 B per A stage
#define BSTG (64 * RSTRIDE)             //  9216 B per B stage
#define SMEM_GEMM (2 * (ASTG + BSTG))   // 55296 B

#define CORE_LOAD(AP, BP, k0_, st_) do {                                          \
    _Pragma("unroll")                                                             \
    for (int i_ = 0; i_ < 4; i_++) {                                              \
        int idx_ = t + i_ * 256;                                                  \
        int r_ = idx_ >> 3, c_ = idx_ & 7;                                        \
        cpa16(asb + (st_)*ASTG + r_*RSTRIDE + c_*16,                              \
              &(AP)[(size_t)(m0 + r_) * 1024 + (k0_) + c_*8]);                    \
    }                                                                             \
    _Pragma("unroll")                                                             \
    for (int i_ = 0; i_ < 2; i_++) {                                              \
        int idx_ = t + i_ * 256;                                                  \
        int r_ = idx_ >> 3, c_ = idx_ & 7;                                        \
        cpa16(bsb + (st_)*BSTG + r_*RSTRIDE + c_*16,                              \
              &(BP)[(size_t)(n0 + r_) * 1024 + (k0_) + c_*8]);                    \
    }                                                                             \
} while(0)

#define CORE_COMPUTE(st_) do {                                                    \
    const unsigned oa = (st_) * (unsigned)ASTG;                                   \
    const unsigned ob = (st_) * (unsigned)BSTG;                                   \
    _Pragma("unroll")                                                             \
    for (int ks = 0; ks < 4; ks++) {                                              \
        const unsigned cb = ks * 32;                                              \
        unsigned a0[4], a1[4], b0[4], b1[4];                                      \
        ldm4(a0, adrA0 + oa + cb);                                                \
        ldm4(a1, adrA1 + oa + cb);                                                \
        ldm4(b0, adrB + ob + cb);                                                 \
        ldm4(b1, adrB + ob + cb + 16);                                            \
        _Pragma("unroll")                                                         \
        for (int nt = 0; nt < 4; nt++) {                                          \
            unsigned bb[2] = { b0[nt], b1[nt] };                                  \
            mma16(Co[0][nt], a0, bb);                                             \
            mma16(Co[1][nt], a1, bb);                                             \
        }                                                                         \
    }                                                                             \
} while(0)

// 2-stage, one barrier per iter; load of tile kt+1 overlaps compute of kt.
#define CORE_MAINLOOP(AP, BP)                                                     \
    CORE_LOAD(AP, BP, 0, 0); CP_COMMIT();                                         \
    _Pragma("unroll 2")                                                           \
    for (int kt = 0; kt < 16; kt++) {                                             \
        CP_WAIT0();                                                               \
        __syncthreads();                                                          \
        if (kt + 1 < 16) { CORE_LOAD(AP, BP, (kt + 1) * 64, (kt + 1) & 1); CP_COMMIT(); } \
        CORE_COMPUTE(kt & 1);                                                     \
    }

// ---------------- fused projection GEMM + l2norm + head scatter ------------
__global__ __launch_bounds__(256) void proj_gemm(
    const __half* __restrict__ A, const __half* __restrict__ Bt,
    __half* __restrict__ gq, __half* __restrict__ gk, __half* __restrict__ gv)
{
    extern __shared__ unsigned char dynsmem[];
    __shared__ float sq[128][4];

    const int t = threadIdx.x;
    const int w = t >> 5, lane = t & 31, g = lane >> 2, tig = lane & 3;
    const int wm = (w >> 1) * 32, wn = (w & 1) * 32;
    const int m0 = blockIdx.y * 128, n0 = blockIdx.x * 64;
    const int li = lane & 7, lj = lane >> 3;

    const unsigned asb = sptr(dynsmem);
    const unsigned bsb = asb + 2 * ASTG;
    const unsigned adrA0 = asb + (wm + (lj & 1) * 8 + li) * RSTRIDE + (lj >> 1) * 16;
    const unsigned adrA1 = adrA0 + 16 * RSTRIDE;
    const unsigned adrB  = bsb + (wn + lj * 8 + li) * RSTRIDE;

    float Co[2][4][4] = {};
    CORE_MAINLOOP(A, Bt)

    // ---- epilogue: group sums of squares (R5-proven) ----
    #pragma unroll
    for (int mt = 0; mt < 2; mt++) {
        float pA0 = 0, pA1 = 0, pB0 = 0, pB1 = 0;
        #pragma unroll
        for (int nt = 0; nt < 2; nt++) {
            pA0 += Co[mt][nt][0]*Co[mt][nt][0] + Co[mt][nt][1]*Co[mt][nt][1];
            pA1 += Co[mt][nt][2]*Co[mt][nt][2] + Co[mt][nt][3]*Co[mt][nt][3];
            pB0 += Co[mt][nt+2][0]*Co[mt][nt+2][0] + Co[mt][nt+2][1]*Co[mt][nt+2][1];
            pB1 += Co[mt][nt+2][2]*Co[mt][nt+2][2] + Co[mt][nt+2][3]*Co[mt][nt+2][3];
        }
        pA0 += __shfl_xor_sync(~0u, pA0, 1); pA0 += __shfl_xor_sync(~0u, pA0, 2);
        pA1 += __shfl_xor_sync(~0u, pA1, 1); pA1 += __shfl_xor_sync(~0u, pA1, 2);
        pB0 += __shfl_xor_sync(~0u, pB0, 1); pB0 += __shfl_xor_sync(~0u, pB0, 2);
        pB1 += __shfl_xor_sync(~0u, pB1, 1); pB1 += __shfl_xor_sync(~0u, pB1, 2);
        if (tig == 0) {
            int r = wm + mt * 16 + g;
            sq[r    ][2*(w&1)    ] = pA0;
            sq[r    ][2*(w&1) + 1] = pB0;
            sq[r + 8][2*(w&1)    ] = pA1;
            sq[r + 8][2*(w&1) + 1] = pB1;
        }
    }
    __syncthreads();

    const int region = (n0 < 256) ? 0 : (n0 < 512 ? 1 : 2);
    #pragma unroll
    for (int mt = 0; mt < 2; mt++)
        #pragma unroll
        for (int rh = 0; rh < 2; rh++) {
            const int r = wm + mt * 16 + g + rh * 8;
            const int m = m0 + r;
            const int b_ = m >> 11, seq = m & (SEQ - 1);
            float scv = 0.f;
            if (region == 2) {
                float ss = sq[r][0] + sq[r][1] + sq[r][2] + sq[r][3];
                scv = 1.f / fmaxf(sqrtf(ss), 1e-12f);
            }
            #pragma unroll
            for (int nt = 0; nt < 4; nt++) {
                float sc;
                if (region == 2) sc = scv;
                else {
                    int grp = 2 * (w & 1) + (nt >> 1);
                    sc = 1.f / fmaxf(sqrtf(sq[r][grp]), 1e-12f);
                }
                const int n = n0 + wn + nt * 8 + 2 * tig;
                unsigned pv = packh2(Co[mt][nt][2*rh] * sc, Co[mt][nt][2*rh+1] * sc);
                if (region == 0) {
                    int h = n >> 4, d = n & 15;
                    *(unsigned*)&gq[((size_t)(b_*NH + h) * SEQ + seq) * DKH + d] = pv;
                } else if (region == 1) {
                    int j = n - 256, h = j >> 4, d = j & 15;
                    *(unsigned*)&gk[((size_t)(b_*NH + h) * SEQ + seq) * DKH + d] = pv;
                } else {
                    int j = n - 512, h = j >> 6, d = j & 63;
                    *(unsigned*)&gv[((size_t)(b_*NH + h) * SEQ + seq) * DVH + d] = pv;
                }
            }
        }
}

// ---------------- final GEMM: C_f32[4096x1024] = A @ Bt^T (K=1024) ---------
__global__ __launch_bounds__(256) void gemm_f16(
    const __half* __restrict__ A, const __half* __restrict__ Bt,
    float* __restrict__ C)
{
    extern __shared__ unsigned char dynsmem[];

    const int t = threadIdx.x;
    const int w = t >> 5, lane = t & 31, g = lane >> 2, tig = lane & 3;
    const int wm = (w >> 1) * 32, wn = (w & 1) * 32;
    const int m0 = blockIdx.y * 128, n0 = blockIdx.x * 64;
    const int li = lane & 7, lj = lane >> 3;

    const unsigned asb = sptr(dynsmem);
    const unsigned bsb = asb + 2 * ASTG;
    const unsigned adrA0 = asb + (wm + (lj & 1) * 8 + li) * RSTRIDE + (lj >> 1) * 16;
    const unsigned adrA1 = adrA0 + 16 * RSTRIDE;
    const unsigned adrB  = bsb + (wn + lj * 8 + li) * RSTRIDE;

    float Co[2][4][4] = {};
    CORE_MAINLOOP(A, Bt)

    #pragma unroll
    for (int mt = 0; mt < 2; mt++)
        #pragma unroll
        for (int nt = 0; nt < 4; nt++) {
            int r = m0 + wm + mt * 16 + g;
            int c = n0 + wn + nt * 8 + 2 * tig;
            *(float2*)&C[(size_t)r * DIM + c]       = make_float2(Co[mt][nt][0], Co[mt][nt][1]);
            *(float2*)&C[(size_t)(r + 8) * DIM + c] = make_float2(Co[mt][nt][2], Co[mt][nt][3]);
        }
}

// ---------------- fused attention: register-resident S (R5-proven) --------
#define AQS  12
#define AVSH 72
__global__ __launch_bounds__(256) void attn_f16(
    const __half* __restrict__ gq, const __half* __restrict__ gk,
    const __half* __restrict__ gv, __half* __restrict__ gao)
{
    __shared__ unsigned Qs[128][AQS];
    __shared__ unsigned Ks[2][64][AQS];
    __shared__ __half   Vs[2][64][AVSH];

    const int t = threadIdx.x;
    const int w = t >> 5, lane = t & 31, g = lane >> 2, tig = lane & 3;
    const int wm = w * 16;
    const int bh = blockIdx.y, q0 = blockIdx.x * 128;
    const int li = lane & 7, lj = lane >> 3;

    const __half* qb = gq + (size_t)bh * SEQ * DKH;
    const __half* kb = gk + (size_t)bh * SEQ * DKH;
    const __half* vb = gv + (size_t)bh * SEQ * DVH;

    {
        int r = t >> 1, hf = t & 1;
        *(uint4*)&Qs[r][hf * 4] = *(const uint4*)&qb[(size_t)(q0 + r) * DKH + hf * 8];
    }

    const int kr = t >> 1, khf = t & 1;
    const int vr = t >> 3, vc = (t & 7) * 8;
    #define ATTN_LOAD(k0_, buf_) do {                                            \
        if (t < 128)                                                             \
            cpa16(sptr(&Ks[buf_][kr][khf*4]), &kb[(size_t)((k0_)+kr)*DKH + khf*8]); \
        cpa16(sptr(&Vs[buf_][vr][vc]),      &vb[(size_t)((k0_)+vr)*DVH + vc]);   \
        cpa16(sptr(&Vs[buf_][vr+32][vc]),   &vb[(size_t)((k0_)+vr+32)*DVH + vc]);\
    } while(0)

    ATTN_LOAD(0, 0);
    CP_COMMIT();
    __syncthreads();

    unsigned aq[4];
    ldm4(aq, sptr(&Qs[wm + (lj & 1) * 8 + li][(lj >> 1) * 4]));

    const unsigned KBUF = 64 * AQS * 4, VBUF = 64 * AVSH * 2;
    const unsigned adrK = sptr(&Ks[0][lj * 8 + li][0]);
    const unsigned adrV = sptr(&Vs[0][(lj & 1) * 8 + li][(lj >> 1) * 8]);

    float Co[8][4] = {};

    const int NT = SEQ / 64;
    for (int kt = 0; kt < NT; kt++) {
        CP_WAIT0();
        __syncthreads();
        if (kt + 1 < NT) { ATTN_LOAD((kt + 1) * 64, (kt + 1) & 1); CP_COMMIT(); }
        const unsigned kbase = adrK + (kt & 1) * KBUF;
        const unsigned vbase = adrV + (kt & 1) * VBUF;

        float Cs[8][4] = {};
        {
            unsigned b0[4], b1[4], b2[4], b3[4];
            ldm4(b0, kbase);
            ldm4(b1, kbase + 16);
            ldm4(b2, kbase + 32 * AQS * 4);
            ldm4(b3, kbase + 32 * AQS * 4 + 16);
            #pragma unroll
            for (int nt = 0; nt < 4; nt++) {
                unsigned bA[2] = { b0[nt], b1[nt] };
                unsigned bB[2] = { b2[nt], b3[nt] };
                mma16(Cs[nt],     aq, bA);
                mma16(Cs[4 + nt], aq, bB);
            }
        }

        unsigned sf[4][4];
        #pragma unroll
        for (int ks = 0; ks < 4; ks++) {
            float r0 = Cs[2*ks][0];   r0 = r0 > 0.f ? r0*r0 : 0.f;
            float r1 = Cs[2*ks][1];   r1 = r1 > 0.f ? r1*r1 : 0.f;
            float r2 = Cs[2*ks][2];   r2 = r2 > 0.f ? r2*r2 : 0.f;
            float r3 = Cs[2*ks][3];   r3 = r3 > 0.f ? r3*r3 : 0.f;
            float r4 = Cs[2*ks+1][0]; r4 = r4 > 0.f ? r4*r4 : 0.f;
            float r5 = Cs[2*ks+1][1]; r5 = r5 > 0.f ? r5*r5 : 0.f;
            float r6 = Cs[2*ks+1][2]; r6 = r6 > 0.f ? r6*r6 : 0.f;
            float r7 = Cs[2*ks+1][3]; r7 = r7 > 0.f ? r7*r7 : 0.f;
            sf[ks][0] = packh2(r0, r1);
            sf[ks][1] = packh2(r2, r3);
            sf[ks][2] = packh2(r4, r5);
            sf[ks][3] = packh2(r6, r7);
        }

        #pragma unroll
        for (int ks = 0; ks < 4; ks++) {
            const unsigned vk = vbase + ks * 16 * AVSH * 2;
            #pragma unroll
            for (int j = 0; j < 4; j++) {
                unsigned vv[4];
                ldm4t(vv, vk + j * 32);
                unsigned bA[2] = { vv[0], vv[1] };
                unsigned bB[2] = { vv[2], vv[3] };
                mma16(Co[2*j],     sf[ks], bA);
                mma16(Co[2*j + 1], sf[ks], bB);
            }
        }
        __syncthreads();
    }

    float s0 = 0.f, s1 = 0.f;
    #pragma unroll
    for (int nt = 0; nt < 8; nt++) {
        s0 += Co[nt][0]*Co[nt][0] + Co[nt][1]*Co[nt][1];
        s1 += Co[nt][2]*Co[nt][2] + Co[nt][3]*Co[nt][3];
    }
    s0 += __shfl_xor_sync(~0u, s0, 1); s0 += __shfl_xor_sync(~0u, s0, 2);
    s1 += __shfl_xor_sync(~0u, s1, 1); s1 += __shfl_xor_sync(~0u, s1, 2);
    float n0s = sqrtf(s0), n1s = sqrtf(s1);
    float sc0 = tanhf(n0s) / fmaxf(n0s, 1e-12f);
    float sc1 = tanhf(n1s) / fmaxf(n1s, 1e-12f);

    const int b_ = bh >> 4, h_ = bh & 15;
    const int row0 = q0 + wm + g, row1 = row0 + 8;
    __half* d0 = gao + (size_t)(b_ * SEQ + row0) * OCOLS + h_ * DVH;
    __half* d1 = gao + (size_t)(b_ * SEQ + row1) * OCOLS + h_ * DVH;
    #pragma unroll
    for (int nt = 0; nt < 8; nt++) {
        int c = nt * 8 + 2 * tig;
        *(unsigned*)&d0[c] = packh2(Co[nt][0] * sc0, Co[nt][1] * sc0);
        *(unsigned*)&d1[c] = packh2(Co[nt][2] * sc1, Co[nt][3] * sc1);
    }
}

// ---------------- host launch ----------------
extern "C" void kernel_launch(void* const* d_in, const int* in_sizes, int n_in,
                              void* d_out, int out_size)
{
    const float *tokens = nullptr, *Wq = nullptr, *Wkv = nullptr, *Wout = nullptr;
    for (int i = 0; i < n_in; i++) {
        switch (in_sizes[i]) {
            case NTOK * DIM:   tokens = (const float*)d_in[i]; break;
            case DIM * QCOLS:  Wq     = (const float*)d_in[i]; break;
            case DIM * KVCOLS: Wkv    = (const float*)d_in[i]; break;
            case OCOLS * DIM:  Wout   = (const float*)d_in[i]; break;
        }
    }

    __half *tokh, *wc, *wot, *qn, *kn, *vh, *aoh;
    cudaGetSymbolAddress((void**)&tokh, g_tokh);
    cudaGetSymbolAddress((void**)&wc,   g_wc);
    cudaGetSymbolAddress((void**)&wot,  g_wot);
    cudaGetSymbolAddress((void**)&qn,   g_qn);
    cudaGetSymbolAddress((void**)&kn,   g_kn);
    cudaGetSymbolAddress((void**)&vh,   g_vh);
    cudaGetSymbolAddress((void**)&aoh,  g_aoh);

    cudaFuncSetAttribute(proj_gemm, cudaFuncAttributeMaxDynamicSharedMemorySize, SMEM_GEMM);
    cudaFuncSetAttribute(gemm_f16,  cudaFuncAttributeMaxDynamicSharedMemorySize, SMEM_GEMM);

    cvt_f2h<<<(NTOK*DIM/8 + 255)/256, 256>>>(tokens, tokh, NTOK*DIM/8);
    wprep<<<dim3(PCOLS/32, DIM/32), 256>>>(Wq, Wkv, wc);
    wtrans<<<dim3(DIM/32, OCOLS/32), 256>>>(Wout, wot, DIM, OCOLS);

    proj_gemm<<<dim3(PCOLS/64, NTOK/128), 256, SMEM_GEMM>>>(tokh, wc, qn, kn, vh);

    attn_f16<<<dim3(SEQ/128, BATCH*NH), 256>>>(qn, kn, vh, aoh);

    gemm_f16<<<dim3(DIM/64, NTOK/128), 256, SMEM_GEMM>>>(aoh, wot, (float*)d_out);
}

// round 12
// speedup vs baseline: 1.1287x; 1.0469x over previous
#include <cuda_runtime.h>
#include <cuda_fp16.h>
#include <cmath>

// Problem constants
#define BATCH   2
#define SEQ     2048
#define DIM     1024
#define NH      16
#define DKH     16
#define DVH     64
#define NTOK    (BATCH*SEQ)          // 4096
#define QCOLS   (NH*DKH)             // 256
#define KVCOLS  (NH*(DKH+DVH))       // 1280
#define OCOLS   (NH*DVH)             // 1024
#define PCOLS   1536                 // 256 q + 256 k + 1024 v (permuted)

// ---------------- scratch ----------------
__device__ __half g_tokh[NTOK * DIM];
__device__ __half g_wc  [PCOLS * DIM];
__device__ __half g_wot [DIM * OCOLS];
__device__ __half g_qn[BATCH*NH*SEQ*DKH];
__device__ __half g_kn[BATCH*NH*SEQ*DKH];
__device__ __half g_vh[BATCH*NH*SEQ*DVH];
__device__ __half g_aoh[NTOK * OCOLS];

// ---------------- helpers ----------------
__device__ __forceinline__ unsigned packh2(float a, float b){
    __half2 h = __floats2half2_rn(a, b);
    return *(unsigned*)&h;
}
__device__ __forceinline__ unsigned sptr(const void* p){
    return (unsigned)__cvta_generic_to_shared(p);
}
__device__ __forceinline__ void ldm4(unsigned r[4], unsigned a){
    asm volatile("ldmatrix.sync.aligned.m8n8.x4.shared.b16 {%0,%1,%2,%3}, [%4];"
        : "=r"(r[0]),"=r"(r[1]),"=r"(r[2]),"=r"(r[3]) : "r"(a));
}
__device__ __forceinline__ void ldm4t(unsigned r[4], unsigned a){
    asm volatile("ldmatrix.sync.aligned.m8n8.x4.trans.shared.b16 {%0,%1,%2,%3}, [%4];"
        : "=r"(r[0]),"=r"(r[1]),"=r"(r[2]),"=r"(r[3]) : "r"(a));
}
__device__ __forceinline__ void mma16(float* c, const unsigned* a, const unsigned* b){
    asm volatile("mma.sync.aligned.m16n8k16.row.col.f32.f16.f16.f32 "
        "{%0,%1,%2,%3},{%4,%5,%6,%7},{%8,%9},{%0,%1,%2,%3};\n"
        : "+f"(c[0]),"+f"(c[1]),"+f"(c[2]),"+f"(c[3])
        : "r"(a[0]),"r"(a[1]),"r"(a[2]),"r"(a[3]),"r"(b[0]),"r"(b[1]));
}
__device__ __forceinline__ void cpa16(unsigned dst, const void* src){
    asm volatile("cp.async.cg.shared.global [%0], [%1], 16;" :: "r"(dst), "l"(src));
}
#define CP_COMMIT() asm volatile("cp.async.commit_group;" ::: "memory")
#define CP_WAIT0()  asm volatile("cp.async.wait_group 0;" ::: "memory")

// ---------------- prep kernels ----------------
__global__ __launch_bounds__(256) void cvt_f2h(const float* __restrict__ src,
                                              __half* __restrict__ dst, int n8)
{
    int i = blockIdx.x * blockDim.x + threadIdx.x;
    if (i >= n8) return;
    float4 a = ((const float4*)src)[2*i];
    float4 b = ((const float4*)src)[2*i+1];
    uint4 p = make_uint4(packh2(a.x,a.y), packh2(a.z,a.w),
                         packh2(b.x,b.y), packh2(b.z,b.w));
    ((uint4*)dst)[i] = p;
}

__global__ __launch_bounds__(256) void wprep(const float* __restrict__ Wq,
                                             const float* __restrict__ Wkv,
                                             __half* __restrict__ Wc)
{
    __shared__ float ts[32][33];
    const int n0 = blockIdx.x * 32, k0 = blockIdx.y * 32;
    const int tx = threadIdx.x & 31, ty = threadIdx.x >> 5;
    {
        const int n = n0 + tx;
        const float* W; int c, ld;
        if (n < 256)      { W = Wq;  ld = QCOLS;  c = n; }
        else if (n < 512) { int j = n - 256; W = Wkv; ld = KVCOLS; c = (j >> 4) * 80 + (j & 15); }
        else              { int j = n - 512; W = Wkv; ld = KVCOLS; c = (j >> 6) * 80 + 16 + (j & 63); }
        #pragma unroll
        for (int i = 0; i < 32; i += 8)
            ts[ty + i][tx] = W[(size_t)(k0 + ty + i) * ld + c];
    }
    __syncthreads();
    #pragma unroll
    for (int i = 0; i < 32; i += 8)
        Wc[(size_t)(n0 + ty + i) * DIM + k0 + tx] = __float2half(ts[tx][ty + i]);
}

__global__ __launch_bounds__(256) void wtrans(const float* __restrict__ W,
                                              __half* __restrict__ Wt, int N, int K)
{
    __shared__ float ts[32][33];
    const int n0 = blockIdx.x * 32, k0 = blockIdx.y * 32;
    const int tx = threadIdx.x & 31, ty = threadIdx.x >> 5;
    #pragma unroll
    for (int i = 0; i < 32; i += 8)
        ts[ty + i][tx] = W[(size_t)(k0 + ty + i) * N + n0 + tx];
    __syncthreads();
    #pragma unroll
    for (int i = 0; i < 32; i += 8)
        Wt[(size_t)(n0 + ty + i) * K + k0 + tx] = __float2half(ts[tx][ty + i]);
}

// ====== GEMM core: 128x64 block, 8 warps, warp 32x32, BK=64, 2 stages =====
// Row stride 144B. Pointer-increment loader; 3 CTAs/SM via launch_bounds.
#define RSTRIDE 144
#define ASTG (128 * RSTRIDE)            // 18432 B per A stage
#define BSTG (64 * RSTRIDE)             //  9216 B per B stage
#define SMEM_GEMM (2 * (ASTG + BSTG))   // 55296 B

// per-thread loader state: row = t>>3 (+32*i), 16B chunk = t&7
#define CORE_DECL_LOADER(AP, BP)                                                  \
    const int lrow = t >> 3, lc8 = (t & 7) * 8;                                   \
    const __half* gA0 = (AP) + (size_t)(m0 + lrow      ) * 1024 + lc8;            \
    const __half* gA1 = (AP) + (size_t)(m0 + lrow + 32 ) * 1024 + lc8;            \
    const __half* gA2 = (AP) + (size_t)(m0 + lrow + 64 ) * 1024 + lc8;            \
    const __half* gA3 = (AP) + (size_t)(m0 + lrow + 96 ) * 1024 + lc8;            \
    const __half* gB0 = (BP) + (size_t)(n0 + lrow      ) * 1024 + lc8;            \
    const __half* gB1 = (BP) + (size_t)(n0 + lrow + 32 ) * 1024 + lc8;            \
    const unsigned sA0 = asb + (lrow      ) * RSTRIDE + (t & 7) * 16;             \
    const unsigned sA1 = asb + (lrow + 32 ) * RSTRIDE + (t & 7) * 16;             \
    const unsigned sA2 = asb + (lrow + 64 ) * RSTRIDE + (t & 7) * 16;             \
    const unsigned sA3 = asb + (lrow + 96 ) * RSTRIDE + (t & 7) * 16;             \
    const unsigned sB0 = bsb + (lrow      ) * RSTRIDE + (t & 7) * 16;             \
    const unsigned sB1 = bsb + (lrow + 32 ) * RSTRIDE + (t & 7) * 16;

#define CORE_LOAD(soff)  do {                                                     \
    cpa16(sA0 + (soff)*ASTG, gA0);  cpa16(sA1 + (soff)*ASTG, gA1);                \
    cpa16(sA2 + (soff)*ASTG, gA2);  cpa16(sA3 + (soff)*ASTG, gA3);                \
    cpa16(sB0 + (soff)*BSTG, gB0);  cpa16(sB1 + (soff)*BSTG, gB1);                \
    gA0 += 64; gA1 += 64; gA2 += 64; gA3 += 64; gB0 += 64; gB1 += 64;             \
} while(0)

#define CORE_COMPUTE(st_) do {                                                    \
    const unsigned oa = (st_) * (unsigned)ASTG;                                   \
    const unsigned ob = (st_) * (unsigned)BSTG;                                   \
    _Pragma("unroll")                                                             \
    for (int ks = 0; ks < 4; ks++) {                                              \
        const unsigned cb = ks * 32;                                              \
        unsigned a0[4], a1[4], b0[4], b1[4];                                      \
        ldm4(a0, adrA0 + oa + cb);                                                \
        ldm4(a1, adrA1 + oa + cb);                                                \
        ldm4(b0, adrB + ob + cb);                                                 \
        ldm4(b1, adrB + ob + cb + 16);                                            \
        _Pragma("unroll")                                                         \
        for (int nt = 0; nt < 4; nt++) {                                          \
            unsigned bb[2] = { b0[nt], b1[nt] };                                  \
            mma16(Co[0][nt], a0, bb);                                             \
            mma16(Co[1][nt], a1, bb);                                             \
        }                                                                         \
    }                                                                             \
} while(0)

#define CORE_MAINLOOP()                                                           \
    CORE_LOAD(0); CP_COMMIT();                                                    \
    _Pragma("unroll 2")                                                           \
    for (int kt = 0; kt < 16; kt++) {                                             \
        CP_WAIT0();                                                               \
        __syncthreads();                                                          \
        if (kt + 1 < 16) { CORE_LOAD((kt + 1) & 1); CP_COMMIT(); }                \
        CORE_COMPUTE(kt & 1);                                                     \
    }

// ---------------- fused projection GEMM + l2norm + head scatter ------------
__global__ __launch_bounds__(256, 3) void proj_gemm(
    const __half* __restrict__ A, const __half* __restrict__ Bt,
    __half* __restrict__ gq, __half* __restrict__ gk, __half* __restrict__ gv)
{
    extern __shared__ unsigned char dynsmem[];
    __shared__ float sq[128][4];

    const int t = threadIdx.x;
    const int w = t >> 5, lane = t & 31, g = lane >> 2, tig = lane & 3;
    const int wm = (w >> 1) * 32, wn = (w & 1) * 32;
    const int m0 = blockIdx.y * 128, n0 = blockIdx.x * 64;
    const int li = lane & 7, lj = lane >> 3;

    const unsigned asb = sptr(dynsmem);
    const unsigned bsb = asb + 2 * ASTG;
    const unsigned adrA0 = asb + (wm + (lj & 1) * 8 + li) * RSTRIDE + (lj >> 1) * 16;
    const unsigned adrA1 = adrA0 + 16 * RSTRIDE;
    const unsigned adrB  = bsb + (wn + lj * 8 + li) * RSTRIDE;

    CORE_DECL_LOADER(A, Bt)
    float Co[2][4][4] = {};
    CORE_MAINLOOP()

    // ---- epilogue: group sums of squares (R5-proven) ----
    #pragma unroll
    for (int mt = 0; mt < 2; mt++) {
        float pA0 = 0, pA1 = 0, pB0 = 0, pB1 = 0;
        #pragma unroll
        for (int nt = 0; nt < 2; nt++) {
            pA0 += Co[mt][nt][0]*Co[mt][nt][0] + Co[mt][nt][1]*Co[mt][nt][1];
            pA1 += Co[mt][nt][2]*Co[mt][nt][2] + Co[mt][nt][3]*Co[mt][nt][3];
            pB0 += Co[mt][nt+2][0]*Co[mt][nt+2][0] + Co[mt][nt+2][1]*Co[mt][nt+2][1];
            pB1 += Co[mt][nt+2][2]*Co[mt][nt+2][2] + Co[mt][nt+2][3]*Co[mt][nt+2][3];
        }
        pA0 += __shfl_xor_sync(~0u, pA0, 1); pA0 += __shfl_xor_sync(~0u, pA0, 2);
        pA1 += __shfl_xor_sync(~0u, pA1, 1); pA1 += __shfl_xor_sync(~0u, pA1, 2);
        pB0 += __shfl_xor_sync(~0u, pB0, 1); pB0 += __shfl_xor_sync(~0u, pB0, 2);
        pB1 += __shfl_xor_sync(~0u, pB1, 1); pB1 += __shfl_xor_sync(~0u, pB1, 2);
        if (tig == 0) {
            int r = wm + mt * 16 + g;
            sq[r    ][2*(w&1)    ] = pA0;
            sq[r    ][2*(w&1) + 1] = pB0;
            sq[r + 8][2*(w&1)    ] = pA1;
            sq[r + 8][2*(w&1) + 1] = pB1;
        }
    }
    __syncthreads();

    const int region = (n0 < 256) ? 0 : (n0 < 512 ? 1 : 2);
    #pragma unroll
    for (int mt = 0; mt < 2; mt++)
        #pragma unroll
        for (int rh = 0; rh < 2; rh++) {
            const int r = wm + mt * 16 + g + rh * 8;
            const int m = m0 + r;
            const int b_ = m >> 11, seq = m & (SEQ - 1);
            float scv = 0.f;
            if (region == 2) {
                float ss = sq[r][0] + sq[r][1] + sq[r][2] + sq[r][3];
                scv = 1.f / fmaxf(sqrtf(ss), 1e-12f);
            }
            #pragma unroll
            for (int nt = 0; nt < 4; nt++) {
                float sc;
                if (region == 2) sc = scv;
                else {
                    int grp = 2 * (w & 1) + (nt >> 1);
                    sc = 1.f / fmaxf(sqrtf(sq[r][grp]), 1e-12f);
                }
                const int n = n0 + wn + nt * 8 + 2 * tig;
                unsigned pv = packh2(Co[mt][nt][2*rh] * sc, Co[mt][nt][2*rh+1] * sc);
                if (region == 0) {
                    int h = n >> 4, d = n & 15;
                    *(unsigned*)&gq[((size_t)(b_*NH + h) * SEQ + seq) * DKH + d] = pv;
                } else if (region == 1) {
                    int j = n - 256, h = j >> 4, d = j & 15;
                    *(unsigned*)&gk[((size_t)(b_*NH + h) * SEQ + seq) * DKH + d] = pv;
                } else {
                    int j = n - 512, h = j >> 6, d = j & 63;
                    *(unsigned*)&gv[((size_t)(b_*NH + h) * SEQ + seq) * DVH + d] = pv;
                }
            }
        }
}

// ---------------- final GEMM: C_f32[4096x1024] = A @ Bt^T (K=1024) ---------
__global__ __launch_bounds__(256, 3) void gemm_f16(
    const __half* __restrict__ A, const __half* __restrict__ Bt,
    float* __restrict__ C)
{
    extern __shared__ unsigned char dynsmem[];

    const int t = threadIdx.x;
    const int w = t >> 5, lane = t & 31, g = lane >> 2, tig = lane & 3;
    const int wm = (w >> 1) * 32, wn = (w & 1) * 32;
    const int m0 = blockIdx.y * 128, n0 = blockIdx.x * 64;
    const int li = lane & 7, lj = lane >> 3;

    const unsigned asb = sptr(dynsmem);
    const unsigned bsb = asb + 2 * ASTG;
    const unsigned adrA0 = asb + (wm + (lj & 1) * 8 + li) * RSTRIDE + (lj >> 1) * 16;
    const unsigned adrA1 = adrA0 + 16 * RSTRIDE;
    const unsigned adrB  = bsb + (wn + lj * 8 + li) * RSTRIDE;

    CORE_DECL_LOADER(A, Bt)
    float Co[2][4][4] = {};
    CORE_MAINLOOP()

    #pragma unroll
    for (int mt = 0; mt < 2; mt++)
        #pragma unroll
        for (int nt = 0; nt < 4; nt++) {
            int r = m0 + wm + mt * 16 + g;
            int c = n0 + wn + nt * 8 + 2 * tig;
            *(float2*)&C[(size_t)r * DIM + c]       = make_float2(Co[mt][nt][0], Co[mt][nt][1]);
            *(float2*)&C[(size_t)(r + 8) * DIM + c] = make_float2(Co[mt][nt][2], Co[mt][nt][3]);
        }
}

// ---------------- fused attention: register-resident S (R5-proven) --------
#define AQS  12
#define AVSH 72
__global__ __launch_bounds__(256) void attn_f16(
    const __half* __restrict__ gq, const __half* __restrict__ gk,
    const __half* __restrict__ gv, __half* __restrict__ gao)
{
    __shared__ unsigned Qs[128][AQS];
    __shared__ unsigned Ks[2][64][AQS];
    __shared__ __half   Vs[2][64][AVSH];

    const int t = threadIdx.x;
    const int w = t >> 5, lane = t & 31, g = lane >> 2, tig = lane & 3;
    const int wm = w * 16;
    const int bh = blockIdx.y, q0 = blockIdx.x * 128;
    const int li = lane & 7, lj = lane >> 3;

    const __half* qb = gq + (size_t)bh * SEQ * DKH;
    const __half* kb = gk + (size_t)bh * SEQ * DKH;
    const __half* vb = gv + (size_t)bh * SEQ * DVH;

    {
        int r = t >> 1, hf = t & 1;
        *(uint4*)&Qs[r][hf * 4] = *(const uint4*)&qb[(size_t)(q0 + r) * DKH + hf * 8];
    }

    const int kr = t >> 1, khf = t & 1;
    const int vr = t >> 3, vc = (t & 7) * 8;
    #define ATTN_LOAD(k0_, buf_) do {                                            \
        if (t < 128)                                                             \
            cpa16(sptr(&Ks[buf_][kr][khf*4]), &kb[(size_t)((k0_)+kr)*DKH + khf*8]); \
        cpa16(sptr(&Vs[buf_][vr][vc]),      &vb[(size_t)((k0_)+vr)*DVH + vc]);   \
        cpa16(sptr(&Vs[buf_][vr+32][vc]),   &vb[(size_t)((k0_)+vr+32)*DVH + vc]);\
    } while(0)

    ATTN_LOAD(0, 0);
    CP_COMMIT();
    __syncthreads();

    unsigned aq[4];
    ldm4(aq, sptr(&Qs[wm + (lj & 1) * 8 + li][(lj >> 1) * 4]));

    const unsigned KBUF = 64 * AQS * 4, VBUF = 64 * AVSH * 2;
    const unsigned adrK = sptr(&Ks[0][lj * 8 + li][0]);
    const unsigned adrV = sptr(&Vs[0][(lj & 1) * 8 + li][(lj >> 1) * 8]);

    float Co[8][4] = {};

    const int NT = SEQ / 64;
    for (int kt = 0; kt < NT; kt++) {
        CP_WAIT0();
        __syncthreads();
        if (kt + 1 < NT) { ATTN_LOAD((kt + 1) * 64, (kt + 1) & 1); CP_COMMIT(); }
        const unsigned kbase = adrK + (kt & 1) * KBUF;
        const unsigned vbase = adrV + (kt & 1) * VBUF;

        float Cs[8][4] = {};
        {
            unsigned b0[4], b1[4], b2[4], b3[4];
            ldm4(b0, kbase);
            ldm4(b1, kbase + 16);
            ldm4(b2, kbase + 32 * AQS * 4);
            ldm4(b3, kbase + 32 * AQS * 4 + 16);
            #pragma unroll
            for (int nt = 0; nt < 4; nt++) {
                unsigned bA[2] = { b0[nt], b1[nt] };
                unsigned bB[2] = { b2[nt], b3[nt] };
                mma16(Cs[nt],     aq, bA);
                mma16(Cs[4 + nt], aq, bB);
            }
        }

        unsigned sf[4][4];
        #pragma unroll
        for (int ks = 0; ks < 4; ks++) {
            float r0 = Cs[2*ks][0];   r0 = r0 > 0.f ? r0*r0 : 0.f;
            float r1 = Cs[2*ks][1];   r1 = r1 > 0.f ? r1*r1 : 0.f;
            float r2 = Cs[2*ks][2];   r2 = r2 > 0.f ? r2*r2 : 0.f;
            float r3 = Cs[2*ks][3];   r3 = r3 > 0.f ? r3*r3 : 0.f;
            float r4 = Cs[2*ks+1][0]; r4 = r4 > 0.f ? r4*r4 : 0.f;
            float r5 = Cs[2*ks+1][1]; r5 = r5 > 0.f ? r5*r5 : 0.f;
            float r6 = Cs[2*ks+1][2]; r6 = r6 > 0.f ? r6*r6 : 0.f;
            float r7 = Cs[2*ks+1][3]; r7 = r7 > 0.f ? r7*r7 : 0.f;
            sf[ks][0] = packh2(r0, r1);
            sf[ks][1] = packh2(r2, r3);
            sf[ks][2] = packh2(r4, r5);
            sf[ks][3] = packh2(r6, r7);
        }

        #pragma unroll
        for (int ks = 0; ks < 4; ks++) {
            const unsigned vk = vbase + ks * 16 * AVSH * 2;
            #pragma unroll
            for (int j = 0; j < 4; j++) {
                unsigned vv[4];
                ldm4t(vv, vk + j * 32);
                unsigned bA[2] = { vv[0], vv[1] };
                unsigned bB[2] = { vv[2], vv[3] };
                mma16(Co[2*j],     sf[ks], bA);
                mma16(Co[2*j + 1], sf[ks], bB);
            }
        }
        __syncthreads();
    }

    float s0 = 0.f, s1 = 0.f;
    #pragma unroll
    for (int nt = 0; nt < 8; nt++) {
        s0 += Co[nt][0]*Co[nt][0] + Co[nt][1]*Co[nt][1];
        s1 += Co[nt][2]*Co[nt][2] + Co[nt][3]*Co[nt][3];
    }
    s0 += __shfl_xor_sync(~0u, s0, 1); s0 += __shfl_xor_sync(~0u, s0, 2);
    s1 += __shfl_xor_sync(~0u, s1, 1); s1 += __shfl_xor_sync(~0u, s1, 2);
    float n0s = sqrtf(s0), n1s = sqrtf(s1);
    float sc0 = tanhf(n0s) / fmaxf(n0s, 1e-12f);
    float sc1 = tanhf(n1s) / fmaxf(n1s, 1e-12f);

    const int b_ = bh >> 4, h_ = bh & 15;
    const int row0 = q0 + wm + g, row1 = row0 + 8;
    __half* d0 = gao + (size_t)(b_ * SEQ + row0) * OCOLS + h_ * DVH;
    __half* d1 = gao + (size_t)(b_ * SEQ + row1) * OCOLS + h_ * DVH;
    #pragma unroll
    for (int nt = 0; nt < 8; nt++) {
        int c = nt * 8 + 2 * tig;
        *(unsigned*)&d0[c] = packh2(Co[nt][0] * sc0, Co[nt][1] * sc0);
        *(unsigned*)&d1[c] = packh2(Co[nt][2] * sc1, Co[nt][3] * sc1);
    }
}

// ---------------- host launch ----------------
extern "C" void kernel_launch(void* const* d_in, const int* in_sizes, int n_in,
                              void* d_out, int out_size)
{
    const float *tokens = nullptr, *Wq = nullptr, *Wkv = nullptr, *Wout = nullptr;
    for (int i = 0; i < n_in; i++) {
        switch (in_sizes[i]) {
            case NTOK * DIM:   tokens = (const float*)d_in[i]; break;
            case DIM * QCOLS:  Wq     = (const float*)d_in[i]; break;
            case DIM * KVCOLS: Wkv    = (const float*)d_in[i]; break;
            case OCOLS * DIM:  Wout   = (const float*)d_in[i]; break;
        }
    }

    __half *tokh, *wc, *wot, *qn, *kn, *vh, *aoh;
    cudaGetSymbolAddress((void**)&tokh, g_tokh);
    cudaGetSymbolAddress((void**)&wc,   g_wc);
    cudaGetSymbolAddress((void**)&wot,  g_wot);
    cudaGetSymbolAddress((void**)&qn,   g_qn);
    cudaGetSymbolAddress((void**)&kn,   g_kn);
    cudaGetSymbolAddress((void**)&vh,   g_vh);
    cudaGetSymbolAddress((void**)&aoh,  g_aoh);

    cudaFuncSetAttribute(proj_gemm, cudaFuncAttributeMaxDynamicSharedMemorySize, SMEM_GEMM);
    cudaFuncSetAttribute(gemm_f16,  cudaFuncAttributeMaxDynamicSharedMemorySize, SMEM_GEMM);

    cvt_f2h<<<(NTOK*DIM/8 + 255)/256, 256>>>(tokens, tokh, NTOK*DIM/8);
    wprep<<<dim3(PCOLS/32, DIM/32), 256>>>(Wq, Wkv, wc);
    wtrans<<<dim3(DIM/32, OCOLS/32), 256>>>(Wout, wot, DIM, OCOLS);

    proj_gemm<<<dim3(PCOLS/64, NTOK/128), 256, SMEM_GEMM>>>(tokh, wc, qn, kn, vh);

    attn_f16<<<dim3(SEQ/128, BATCH*NH), 256>>>(qn, kn, vh, aoh);

    gemm_f16<<<dim3(DIM/64, NTOK/128), 256, SMEM_GEMM>>>(aoh, wot, (float*)d_out);
}

// round 13
// speedup vs baseline: 1.1417x; 1.0115x over previous
#include <cuda_runtime.h>
#include <cuda_fp16.h>
#include <cmath>

// Problem constants
#define BATCH   2
#define SEQ     2048
#define DIM     1024
#define NH      16
#define DKH     16
#define DVH     64
#define NTOK    (BATCH*SEQ)          // 4096
#define QCOLS   (NH*DKH)             // 256
#define KVCOLS  (NH*(DKH+DVH))       // 1280
#define OCOLS   (NH*DVH)             // 1024
#define PCOLS   1536                 // 256 q + 256 k + 1024 v (permuted)

// ---------------- scratch ----------------
__device__ __half g_tokh[NTOK * DIM];
__device__ __half g_wc  [PCOLS * DIM];
__device__ __half g_wot [DIM * OCOLS];
__device__ __half g_qn[BATCH*NH*SEQ*DKH];
__device__ __half g_kn[BATCH*NH*SEQ*DKH];
__device__ __half g_vh[BATCH*NH*SEQ*DVH];
__device__ __half g_aoh[NTOK * OCOLS];

// ---------------- helpers ----------------
__device__ __forceinline__ unsigned packh2(float a, float b){
    __half2 h = __floats2half2_rn(a, b);
    return *(unsigned*)&h;
}
__device__ __forceinline__ unsigned sptr(const void* p){
    return (unsigned)__cvta_generic_to_shared(p);
}
__device__ __forceinline__ void ldm4(unsigned r[4], unsigned a){
    asm volatile("ldmatrix.sync.aligned.m8n8.x4.shared.b16 {%0,%1,%2,%3}, [%4];"
        : "=r"(r[0]),"=r"(r[1]),"=r"(r[2]),"=r"(r[3]) : "r"(a));
}
__device__ __forceinline__ void ldm4t(unsigned r[4], unsigned a){
    asm volatile("ldmatrix.sync.aligned.m8n8.x4.trans.shared.b16 {%0,%1,%2,%3}, [%4];"
        : "=r"(r[0]),"=r"(r[1]),"=r"(r[2]),"=r"(r[3]) : "r"(a));
}
__device__ __forceinline__ void mma16(float* c, const unsigned* a, const unsigned* b){
    asm volatile("mma.sync.aligned.m16n8k16.row.col.f32.f16.f16.f32 "
        "{%0,%1,%2,%3},{%4,%5,%6,%7},{%8,%9},{%0,%1,%2,%3};\n"
        : "+f"(c[0]),"+f"(c[1]),"+f"(c[2]),"+f"(c[3])
        : "r"(a[0]),"r"(a[1]),"r"(a[2]),"r"(a[3]),"r"(b[0]),"r"(b[1]));
}
__device__ __forceinline__ void cpa16(unsigned dst, const void* src){
    asm volatile("cp.async.cg.shared.global [%0], [%1], 16;" :: "r"(dst), "l"(src));
}
#define CP_COMMIT() asm volatile("cp.async.commit_group;" ::: "memory")
#define CP_WAIT0()  asm volatile("cp.async.wait_group 0;" ::: "memory")

// ---------------- prep kernels ----------------
__global__ __launch_bounds__(256) void cvt_f2h(const float* __restrict__ src,
                                              __half* __restrict__ dst, int n8)
{
    int i = blockIdx.x * blockDim.x + threadIdx.x;
    if (i >= n8) return;
    float4 a = ((const float4*)src)[2*i];
    float4 b = ((const float4*)src)[2*i+1];
    uint4 p = make_uint4(packh2(a.x,a.y), packh2(a.z,a.w),
                         packh2(b.x,b.y), packh2(b.z,b.w));
    ((uint4*)dst)[i] = p;
}

__global__ __launch_bounds__(256) void wprep(const float* __restrict__ Wq,
                                             const float* __restrict__ Wkv,
                                             __half* __restrict__ Wc)
{
    __shared__ float ts[32][33];
    const int n0 = blockIdx.x * 32, k0 = blockIdx.y * 32;
    const int tx = threadIdx.x & 31, ty = threadIdx.x >> 5;
    {
        const int n = n0 + tx;
        const float* W; int c, ld;
        if (n < 256)      { W = Wq;  ld = QCOLS;  c = n; }
        else if (n < 512) { int j = n - 256; W = Wkv; ld = KVCOLS; c = (j >> 4) * 80 + (j & 15); }
        else              { int j = n - 512; W = Wkv; ld = KVCOLS; c = (j >> 6) * 80 + 16 + (j & 63); }
        #pragma unroll
        for (int i = 0; i < 32; i += 8)
            ts[ty + i][tx] = W[(size_t)(k0 + ty + i) * ld + c];
    }
    __syncthreads();
    #pragma unroll
    for (int i = 0; i < 32; i += 8)
        Wc[(size_t)(n0 + ty + i) * DIM + k0 + tx] = __float2half(ts[tx][ty + i]);
}

__global__ __launch_bounds__(256) void wtrans(const float* __restrict__ W,
                                              __half* __restrict__ Wt, int N, int K)
{
    __shared__ float ts[32][33];
    const int n0 = blockIdx.x * 32, k0 = blockIdx.y * 32;
    const int tx = threadIdx.x & 31, ty = threadIdx.x >> 5;
    #pragma unroll
    for (int i = 0; i < 32; i += 8)
        ts[ty + i][tx] = W[(size_t)(k0 + ty + i) * N + n0 + tx];
    __syncthreads();
    #pragma unroll
    for (int i = 0; i < 32; i += 8)
        Wt[(size_t)(n0 + ty + i) * K + k0 + tx] = __float2half(ts[tx][ty + i]);
}

// ====== GEMM core: 128x64 block, 8 warps, warp 32x32, BK=64, 2 stages =====
#define RSTRIDE 144
#define ASTG (128 * RSTRIDE)            // 18432 B per A stage
#define BSTG (64 * RSTRIDE)             //  9216 B per B stage
#define SMEM_GEMM (2 * (ASTG + BSTG))   // 55296 B

#define CORE_DECL_LOADER(AP, BP)                                                  \
    const int lrow = t >> 3, lc8 = (t & 7) * 8;                                   \
    const __half* gA0 = (AP) + (size_t)(m0 + lrow      ) * 1024 + lc8;            \
    const __half* gA1 = (AP) + (size_t)(m0 + lrow + 32 ) * 1024 + lc8;            \
    const __half* gA2 = (AP) + (size_t)(m0 + lrow + 64 ) * 1024 + lc8;            \
    const __half* gA3 = (AP) + (size_t)(m0 + lrow + 96 ) * 1024 + lc8;            \
    const __half* gB0 = (BP) + (size_t)(n0 + lrow      ) * 1024 + lc8;            \
    const __half* gB1 = (BP) + (size_t)(n0 + lrow + 32 ) * 1024 + lc8;            \
    const unsigned sA0 = asb + (lrow      ) * RSTRIDE + (t & 7) * 16;             \
    const unsigned sA1 = asb + (lrow + 32 ) * RSTRIDE + (t & 7) * 16;             \
    const unsigned sA2 = asb + (lrow + 64 ) * RSTRIDE + (t & 7) * 16;             \
    const unsigned sA3 = asb + (lrow + 96 ) * RSTRIDE + (t & 7) * 16;             \
    const unsigned sB0 = bsb + (lrow      ) * RSTRIDE + (t & 7) * 16;             \
    const unsigned sB1 = bsb + (lrow + 32 ) * RSTRIDE + (t & 7) * 16;

#define CORE_LOAD(soff)  do {                                                     \
    cpa16(sA0 + (soff)*ASTG, gA0);  cpa16(sA1 + (soff)*ASTG, gA1);                \
    cpa16(sA2 + (soff)*ASTG, gA2);  cpa16(sA3 + (soff)*ASTG, gA3);                \
    cpa16(sB0 + (soff)*BSTG, gB0);  cpa16(sB1 + (soff)*BSTG, gB1);                \
    gA0 += 64; gA1 += 64; gA2 += 64; gA3 += 64; gB0 += 64; gB1 += 64;             \
} while(0)

#define CORE_COMPUTE(st_) do {                                                    \
    const unsigned oa = (st_) * (unsigned)ASTG;                                   \
    const unsigned ob = (st_) * (unsigned)BSTG;                                   \
    _Pragma("unroll")                                                             \
    for (int ks = 0; ks < 4; ks++) {                                              \
        const unsigned cb = ks * 32;                                              \
        unsigned a0[4], a1[4], b0[4], b1[4];                                      \
        ldm4(a0, adrA0 + oa + cb);                                                \
        ldm4(a1, adrA1 + oa + cb);                                                \
        ldm4(b0, adrB + ob + cb);                                                 \
        ldm4(b1, adrB + ob + cb + 16);                                            \
        _Pragma("unroll")                                                         \
        for (int nt = 0; nt < 4; nt++) {                                          \
            unsigned bb[2] = { b0[nt], b1[nt] };                                  \
            mma16(Co[0][nt], a0, bb);                                             \
            mma16(Co[1][nt], a1, bb);                                             \
        }                                                                         \
    }                                                                             \
} while(0)

#define CORE_MAINLOOP()                                                           \
    CORE_LOAD(0); CP_COMMIT();                                                    \
    _Pragma("unroll 2")                                                           \
    for (int kt = 0; kt < 16; kt++) {                                             \
        CP_WAIT0();                                                               \
        __syncthreads();                                                          \
        if (kt + 1 < 16) { CORE_LOAD((kt + 1) & 1); CP_COMMIT(); }                \
        CORE_COMPUTE(kt & 1);                                                     \
    }

// ---------------- fused projection GEMM + l2norm + head scatter ------------
__global__ __launch_bounds__(256, 3) void proj_gemm(
    const __half* __restrict__ A, const __half* __restrict__ Bt,
    __half* __restrict__ gq, __half* __restrict__ gk, __half* __restrict__ gv)
{
    extern __shared__ unsigned char dynsmem[];
    __shared__ float sq[128][4];

    const int t = threadIdx.x;
    const int w = t >> 5, lane = t & 31, g = lane >> 2, tig = lane & 3;
    const int wm = (w >> 1) * 32, wn = (w & 1) * 32;
    const int m0 = blockIdx.y * 128, n0 = blockIdx.x * 64;
    const int li = lane & 7, lj = lane >> 3;

    const unsigned asb = sptr(dynsmem);
    const unsigned bsb = asb + 2 * ASTG;
    const unsigned adrA0 = asb + (wm + (lj & 1) * 8 + li) * RSTRIDE + (lj >> 1) * 16;
    const unsigned adrA1 = adrA0 + 16 * RSTRIDE;
    const unsigned adrB  = bsb + (wn + lj * 8 + li) * RSTRIDE;

    CORE_DECL_LOADER(A, Bt)
    float Co[2][4][4] = {};
    CORE_MAINLOOP()

    // ---- epilogue: group sums of squares (R5-proven) ----
    #pragma unroll
    for (int mt = 0; mt < 2; mt++) {
        float pA0 = 0, pA1 = 0, pB0 = 0, pB1 = 0;
        #pragma unroll
        for (int nt = 0; nt < 2; nt++) {
            pA0 += Co[mt][nt][0]*Co[mt][nt][0] + Co[mt][nt][1]*Co[mt][nt][1];
            pA1 += Co[mt][nt][2]*Co[mt][nt][2] + Co[mt][nt][3]*Co[mt][nt][3];
            pB0 += Co[mt][nt+2][0]*Co[mt][nt+2][0] + Co[mt][nt+2][1]*Co[mt][nt+2][1];
            pB1 += Co[mt][nt+2][2]*Co[mt][nt+2][2] + Co[mt][nt+2][3]*Co[mt][nt+2][3];
        }
        pA0 += __shfl_xor_sync(~0u, pA0, 1); pA0 += __shfl_xor_sync(~0u, pA0, 2);
        pA1 += __shfl_xor_sync(~0u, pA1, 1); pA1 += __shfl_xor_sync(~0u, pA1, 2);
        pB0 += __shfl_xor_sync(~0u, pB0, 1); pB0 += __shfl_xor_sync(~0u, pB0, 2);
        pB1 += __shfl_xor_sync(~0u, pB1, 1); pB1 += __shfl_xor_sync(~0u, pB1, 2);
        if (tig == 0) {
            int r = wm + mt * 16 + g;
            sq[r    ][2*(w&1)    ] = pA0;
            sq[r    ][2*(w&1) + 1] = pB0;
            sq[r + 8][2*(w&1)    ] = pA1;
            sq[r + 8][2*(w&1) + 1] = pB1;
        }
    }
    __syncthreads();

    const int region = (n0 < 256) ? 0 : (n0 < 512 ? 1 : 2);
    #pragma unroll
    for (int mt = 0; mt < 2; mt++)
        #pragma unroll
        for (int rh = 0; rh < 2; rh++) {
            const int r = wm + mt * 16 + g + rh * 8;
            const int m = m0 + r;
            const int b_ = m >> 11, seq = m & (SEQ - 1);
            float scv = 0.f;
            if (region == 2) {
                float ss = sq[r][0] + sq[r][1] + sq[r][2] + sq[r][3];
                scv = 1.f / fmaxf(sqrtf(ss), 1e-12f);
            }
            #pragma unroll
            for (int nt = 0; nt < 4; nt++) {
                float sc;
                if (region == 2) sc = scv;
                else {
                    int grp = 2 * (w & 1) + (nt >> 1);
                    sc = 1.f / fmaxf(sqrtf(sq[r][grp]), 1e-12f);
                }
                const int n = n0 + wn + nt * 8 + 2 * tig;
                unsigned pv = packh2(Co[mt][nt][2*rh] * sc, Co[mt][nt][2*rh+1] * sc);
                if (region == 0) {
                    int h = n >> 4, d = n & 15;
                    *(unsigned*)&gq[((size_t)(b_*NH + h) * SEQ + seq) * DKH + d] = pv;
                } else if (region == 1) {
                    int j = n - 256, h = j >> 4, d = j & 15;
                    *(unsigned*)&gk[((size_t)(b_*NH + h) * SEQ + seq) * DKH + d] = pv;
                } else {
                    int j = n - 512, h = j >> 6, d = j & 63;
                    *(unsigned*)&gv[((size_t)(b_*NH + h) * SEQ + seq) * DVH + d] = pv;
                }
            }
        }
}

// ---------------- final GEMM: C_f32[4096x1024] = A @ Bt^T (K=1024) ---------
__global__ __launch_bounds__(256, 3) void gemm_f16(
    const __half* __restrict__ A, const __half* __restrict__ Bt,
    float* __restrict__ C)
{
    extern __shared__ unsigned char dynsmem[];

    const int t = threadIdx.x;
    const int w = t >> 5, lane = t & 31, g = lane >> 2, tig = lane & 3;
    const int wm = (w >> 1) * 32, wn = (w & 1) * 32;
    const int m0 = blockIdx.y * 128, n0 = blockIdx.x * 64;
    const int li = lane & 7, lj = lane >> 3;

    const unsigned asb = sptr(dynsmem);
    const unsigned bsb = asb + 2 * ASTG;
    const unsigned adrA0 = asb + (wm + (lj & 1) * 8 + li) * RSTRIDE + (lj >> 1) * 16;
    const unsigned adrA1 = adrA0 + 16 * RSTRIDE;
    const unsigned adrB  = bsb + (wn + lj * 8 + li) * RSTRIDE;

    CORE_DECL_LOADER(A, Bt)
    float Co[2][4][4] = {};
    CORE_MAINLOOP()

    #pragma unroll
    for (int mt = 0; mt < 2; mt++)
        #pragma unroll
        for (int nt = 0; nt < 4; nt++) {
            int r = m0 + wm + mt * 16 + g;
            int c = n0 + wn + nt * 8 + 2 * tig;
            *(float2*)&C[(size_t)r * DIM + c]       = make_float2(Co[mt][nt][0], Co[mt][nt][1]);
            *(float2*)&C[(size_t)(r + 8) * DIM + c] = make_float2(Co[mt][nt][2], Co[mt][nt][3]);
        }
}

// ---------------- fused attention: register-resident S, 3 CTAs/SM ---------
// S computed in two 32-key halves to cap live registers (~83).
#define AQS  12
#define AVSH 72
__global__ __launch_bounds__(256, 3) void attn_f16(
    const __half* __restrict__ gq, const __half* __restrict__ gk,
    const __half* __restrict__ gv, __half* __restrict__ gao)
{
    __shared__ unsigned Qs[128][AQS];
    __shared__ unsigned Ks[2][64][AQS];
    __shared__ __half   Vs[2][64][AVSH];

    const int t = threadIdx.x;
    const int w = t >> 5, lane = t & 31, g = lane >> 2, tig = lane & 3;
    const int wm = w * 16;
    const int bh = blockIdx.y, q0 = blockIdx.x * 128;
    const int li = lane & 7, lj = lane >> 3;

    const __half* qb = gq + (size_t)bh * SEQ * DKH;
    const __half* kb = gk + (size_t)bh * SEQ * DKH;
    const __half* vb = gv + (size_t)bh * SEQ * DVH;

    {
        int r = t >> 1, hf = t & 1;
        *(uint4*)&Qs[r][hf * 4] = *(const uint4*)&qb[(size_t)(q0 + r) * DKH + hf * 8];
    }

    const int kr = t >> 1, khf = t & 1;
    const int vr = t >> 3, vc = (t & 7) * 8;
    #define ATTN_LOAD(k0_, buf_) do {                                            \
        if (t < 128)                                                             \
            cpa16(sptr(&Ks[buf_][kr][khf*4]), &kb[(size_t)((k0_)+kr)*DKH + khf*8]); \
        cpa16(sptr(&Vs[buf_][vr][vc]),      &vb[(size_t)((k0_)+vr)*DVH + vc]);   \
        cpa16(sptr(&Vs[buf_][vr+32][vc]),   &vb[(size_t)((k0_)+vr+32)*DVH + vc]);\
    } while(0)

    ATTN_LOAD(0, 0);
    CP_COMMIT();
    __syncthreads();

    unsigned aq[4];
    ldm4(aq, sptr(&Qs[wm + (lj & 1) * 8 + li][(lj >> 1) * 4]));

    const unsigned KBUF = 64 * AQS * 4, VBUF = 64 * AVSH * 2;
    const unsigned adrK = sptr(&Ks[0][lj * 8 + li][0]);
    const unsigned adrV = sptr(&Vs[0][(lj & 1) * 8 + li][(lj >> 1) * 8]);

    float Co[8][4] = {};

    const int NT = SEQ / 64;
    for (int kt = 0; kt < NT; kt++) {
        CP_WAIT0();
        __syncthreads();
        if (kt + 1 < NT) { ATTN_LOAD((kt + 1) * 64, (kt + 1) & 1); CP_COMMIT(); }
        const unsigned kbase = adrK + (kt & 1) * KBUF;
        const unsigned vbase = adrV + (kt & 1) * VBUF;

        // ---- S = Q@K^T in two 32-key halves (halves live-register peak) ----
        unsigned sf[4][4];
        #pragma unroll
        for (int hh = 0; hh < 2; hh++) {
            float Cs[4][4] = {};
            unsigned b0[4], b1[4];
            ldm4(b0, kbase + hh * 32 * AQS * 4);
            ldm4(b1, kbase + hh * 32 * AQS * 4 + 16);
            #pragma unroll
            for (int nt = 0; nt < 4; nt++) {
                unsigned bA[2] = { b0[nt], b1[nt] };
                mma16(Cs[nt], aq, bA);
            }
            #pragma unroll
            for (int p = 0; p < 2; p++) {       // key sub-pairs -> sf cols
                float r0 = Cs[2*p][0];   r0 = r0 > 0.f ? r0*r0 : 0.f;
                float r1 = Cs[2*p][1];   r1 = r1 > 0.f ? r1*r1 : 0.f;
                float r2 = Cs[2*p][2];   r2 = r2 > 0.f ? r2*r2 : 0.f;
                float r3 = Cs[2*p][3];   r3 = r3 > 0.f ? r3*r3 : 0.f;
                float r4 = Cs[2*p+1][0]; r4 = r4 > 0.f ? r4*r4 : 0.f;
                float r5 = Cs[2*p+1][1]; r5 = r5 > 0.f ? r5*r5 : 0.f;
                float r6 = Cs[2*p+1][2]; r6 = r6 > 0.f ? r6*r6 : 0.f;
                float r7 = Cs[2*p+1][3]; r7 = r7 > 0.f ? r7*r7 : 0.f;
                sf[hh*2 + p][0] = packh2(r0, r1);
                sf[hh*2 + p][1] = packh2(r2, r3);
                sf[hh*2 + p][2] = packh2(r4, r5);
                sf[hh*2 + p][3] = packh2(r6, r7);
            }
        }

        // ---- Out += S @ V (4 k16 steps) ----
        #pragma unroll
        for (int ks = 0; ks < 4; ks++) {
            const unsigned vk = vbase + ks * 16 * AVSH * 2;
            #pragma unroll
            for (int j = 0; j < 4; j++) {
                unsigned vv[4];
                ldm4t(vv, vk + j * 32);
                unsigned bA[2] = { vv[0], vv[1] };
                unsigned bB[2] = { vv[2], vv[3] };
                mma16(Co[2*j],     sf[ks], bA);
                mma16(Co[2*j + 1], sf[ks], bB);
            }
        }
        __syncthreads();
    }

    float s0 = 0.f, s1 = 0.f;
    #pragma unroll
    for (int nt = 0; nt < 8; nt++) {
        s0 += Co[nt][0]*Co[nt][0] + Co[nt][1]*Co[nt][1];
        s1 += Co[nt][2]*Co[nt][2] + Co[nt][3]*Co[nt][3];
    }
    s0 += __shfl_xor_sync(~0u, s0, 1); s0 += __shfl_xor_sync(~0u, s0, 2);
    s1 += __shfl_xor_sync(~0u, s1, 1); s1 += __shfl_xor_sync(~0u, s1, 2);
    float n0s = sqrtf(s0), n1s = sqrtf(s1);
    float sc0 = tanhf(n0s) / fmaxf(n0s, 1e-12f);
    float sc1 = tanhf(n1s) / fmaxf(n1s, 1e-12f);

    const int b_ = bh >> 4, h_ = bh & 15;
    const int row0 = q0 + wm + g, row1 = row0 + 8;
    __half* d0 = gao + (size_t)(b_ * SEQ + row0) * OCOLS + h_ * DVH;
    __half* d1 = gao + (size_t)(b_ * SEQ + row1) * OCOLS + h_ * DVH;
    #pragma unroll
    for (int nt = 0; nt < 8; nt++) {
        int c = nt * 8 + 2 * tig;
        *(unsigned*)&d0[c] = packh2(Co[nt][0] * sc0, Co[nt][1] * sc0);
        *(unsigned*)&d1[c] = packh2(Co[nt][2] * sc1, Co[nt][3] * sc1);
    }
}

// ---------------- host launch ----------------
extern "C" void kernel_launch(void* const* d_in, const int* in_sizes, int n_in,
                              void* d_out, int out_size)
{
    const float *tokens = nullptr, *Wq = nullptr, *Wkv = nullptr, *Wout = nullptr;
    for (int i = 0; i < n_in; i++) {
        switch (in_sizes[i]) {
            case NTOK * DIM:   tokens = (const float*)d_in[i]; break;
            case DIM * QCOLS:  Wq     = (const float*)d_in[i]; break;
            case DIM * KVCOLS: Wkv    = (const float*)d_in[i]; break;
            case OCOLS * DIM:  Wout   = (const float*)d_in[i]; break;
        }
    }

    __half *tokh, *wc, *wot, *qn, *kn, *vh, *aoh;
    cudaGetSymbolAddress((void**)&tokh, g_tokh);
    cudaGetSymbolAddress((void**)&wc,   g_wc);
    cudaGetSymbolAddress((void**)&wot,  g_wot);
    cudaGetSymbolAddress((void**)&qn,   g_qn);
    cudaGetSymbolAddress((void**)&kn,   g_kn);
    cudaGetSymbolAddress((void**)&vh,   g_vh);
    cudaGetSymbolAddress((void**)&aoh,  g_aoh);

    cudaFuncSetAttribute(proj_gemm, cudaFuncAttributeMaxDynamicSharedMemorySize, SMEM_GEMM);
    cudaFuncSetAttribute(gemm_f16,  cudaFuncAttributeMaxDynamicSharedMemorySize, SMEM_GEMM);

    cvt_f2h<<<(NTOK*DIM/8 + 255)/256, 256>>>(tokens, tokh, NTOK*DIM/8);
    wprep<<<dim3(PCOLS/32, DIM/32), 256>>>(Wq, Wkv, wc);
    wtrans<<<dim3(DIM/32, OCOLS/32), 256>>>(Wout, wot, DIM, OCOLS);

    proj_gemm<<<dim3(PCOLS/64, NTOK/128), 256, SMEM_GEMM>>>(tokh, wc, qn, kn, vh);

    attn_f16<<<dim3(SEQ/128, BATCH*NH), 256>>>(qn, kn, vh, aoh);

    gemm_f16<<<dim3(DIM/64, NTOK/128), 256, SMEM_GEMM>>>(aoh, wot, (float*)d_out);
}

// round 14
// speedup vs baseline: 1.1671x; 1.0222x over previous
#include <cuda_runtime.h>
#include <cuda_fp16.h>
#include <cmath>

// Problem constants
#define BATCH   2
#define SEQ     2048
#define DIM     1024
#define NH      16
#define DKH     16
#define DVH     64
#define NTOK    (BATCH*SEQ)          // 4096
#define QCOLS   (NH*DKH)             // 256
#define KVCOLS  (NH*(DKH+DVH))       // 1280
#define OCOLS   (NH*DVH)             // 1024
#define PCOLS   1536                 // 256 q + 256 k + 1024 v (permuted)

// ---------------- scratch ----------------
__device__ __half g_tokh[NTOK * DIM];
__device__ __half g_wc  [PCOLS * DIM];
__device__ __half g_wot [DIM * OCOLS];
__device__ __half g_qn[BATCH*NH*SEQ*DKH];
__device__ __half g_kn[BATCH*NH*SEQ*DKH];
__device__ __half g_vh[BATCH*NH*SEQ*DVH];
__device__ __half g_aoh[NTOK * OCOLS];

// ---------------- helpers ----------------
__device__ __forceinline__ unsigned packh2(float a, float b){
    __half2 h = __floats2half2_rn(a, b);
    return *(unsigned*)&h;
}
__device__ __forceinline__ unsigned sptr(const void* p){
    return (unsigned)__cvta_generic_to_shared(p);
}
__device__ __forceinline__ void ldm4(unsigned r[4], unsigned a){
    asm volatile("ldmatrix.sync.aligned.m8n8.x4.shared.b16 {%0,%1,%2,%3}, [%4];"
        : "=r"(r[0]),"=r"(r[1]),"=r"(r[2]),"=r"(r[3]) : "r"(a));
}
__device__ __forceinline__ void ldm4t(unsigned r[4], unsigned a){
    asm volatile("ldmatrix.sync.aligned.m8n8.x4.trans.shared.b16 {%0,%1,%2,%3}, [%4];"
        : "=r"(r[0]),"=r"(r[1]),"=r"(r[2]),"=r"(r[3]) : "r"(a));
}
__device__ __forceinline__ void mma16(float* c, const unsigned* a, const unsigned* b){
    asm volatile("mma.sync.aligned.m16n8k16.row.col.f32.f16.f16.f32 "
        "{%0,%1,%2,%3},{%4,%5,%6,%7},{%8,%9},{%0,%1,%2,%3};\n"
        : "+f"(c[0]),"+f"(c[1]),"+f"(c[2]),"+f"(c[3])
        : "r"(a[0]),"r"(a[1]),"r"(a[2]),"r"(a[3]),"r"(b[0]),"r"(b[1]));
}
__device__ __forceinline__ void cpa16(unsigned dst, const void* src){
    asm volatile("cp.async.cg.shared.global [%0], [%1], 16;" :: "r"(dst), "l"(src));
}
#define CP_COMMIT() asm volatile("cp.async.commit_group;" ::: "memory")
#define CP_WAIT0()  asm volatile("cp.async.wait_group 0;" ::: "memory")

// ---------------- fused prep kernel ----------------
// blocks [0, 2048)        : tokens f32 -> f16 (8 elems x 256 thr per block)
// blocks [2048, 3584)     : wprep  (48 x 32 tile grid)
// blocks [3584, 4608)     : wtrans (32 x 32 tile grid)
#define PREP_CVT_BLOCKS   2048
#define PREP_WPREP_BLOCKS 1536
#define PREP_WT_BLOCKS    1024
#define PREP_TOTAL (PREP_CVT_BLOCKS + PREP_WPREP_BLOCKS + PREP_WT_BLOCKS)

__global__ __launch_bounds__(256) void prep_all(
    const float* __restrict__ tokens, const float* __restrict__ Wq,
    const float* __restrict__ Wkv, const float* __restrict__ Wout,
    __half* __restrict__ tokh, __half* __restrict__ Wc, __half* __restrict__ Wt)
{
    __shared__ float ts[32][33];
    const int bid = blockIdx.x;
    const int t = threadIdx.x;

    if (bid < PREP_CVT_BLOCKS) {
        int i = bid * 256 + t;                    // n8 = 524288 total
        float4 a = ((const float4*)tokens)[2*i];
        float4 b = ((const float4*)tokens)[2*i+1];
        uint4 p = make_uint4(packh2(a.x,a.y), packh2(a.z,a.w),
                             packh2(b.x,b.y), packh2(b.z,b.w));
        ((uint4*)tokh)[i] = p;
    } else if (bid < PREP_CVT_BLOCKS + PREP_WPREP_BLOCKS) {
        int jb = bid - PREP_CVT_BLOCKS;
        const int n0 = (jb % 48) * 32, k0 = (jb / 48) * 32;
        const int tx = t & 31, ty = t >> 5;
        {
            const int n = n0 + tx;
            const float* W; int c, ld;
            if (n < 256)      { W = Wq;  ld = QCOLS;  c = n; }
            else if (n < 512) { int j = n - 256; W = Wkv; ld = KVCOLS; c = (j >> 4) * 80 + (j & 15); }
            else              { int j = n - 512; W = Wkv; ld = KVCOLS; c = (j >> 6) * 80 + 16 + (j & 63); }
            #pragma unroll
            for (int i = 0; i < 32; i += 8)
                ts[ty + i][tx] = W[(size_t)(k0 + ty + i) * ld + c];
        }
        __syncthreads();
        #pragma unroll
        for (int i = 0; i < 32; i += 8)
            Wc[(size_t)(n0 + ty + i) * DIM + k0 + tx] = __float2half(ts[tx][ty + i]);
    } else {
        int jb = bid - PREP_CVT_BLOCKS - PREP_WPREP_BLOCKS;
        const int n0 = (jb % 32) * 32, k0 = (jb / 32) * 32;   // N=DIM, K=OCOLS
        const int tx = t & 31, ty = t >> 5;
        #pragma unroll
        for (int i = 0; i < 32; i += 8)
            ts[ty + i][tx] = Wout[(size_t)(k0 + ty + i) * DIM + n0 + tx];
        __syncthreads();
        #pragma unroll
        for (int i = 0; i < 32; i += 8)
            Wt[(size_t)(n0 + ty + i) * OCOLS + k0 + tx] = __float2half(ts[tx][ty + i]);
    }
}

// ====== GEMM core: 128x64 block, 8 warps, warp 32x32, BK=64, 2 stages =====
#define RSTRIDE 144
#define ASTG (128 * RSTRIDE)            // 18432 B per A stage
#define BSTG (64 * RSTRIDE)             //  9216 B per B stage
#define SMEM_GEMM (2 * (ASTG + BSTG))   // 55296 B

#define CORE_DECL_LOADER(AP, BP)                                                  \
    const int lrow = t >> 3, lc8 = (t & 7) * 8;                                   \
    const __half* gA0 = (AP) + (size_t)(m0 + lrow      ) * 1024 + lc8;            \
    const __half* gA1 = (AP) + (size_t)(m0 + lrow + 32 ) * 1024 + lc8;            \
    const __half* gA2 = (AP) + (size_t)(m0 + lrow + 64 ) * 1024 + lc8;            \
    const __half* gA3 = (AP) + (size_t)(m0 + lrow + 96 ) * 1024 + lc8;            \
    const __half* gB0 = (BP) + (size_t)(n0 + lrow      ) * 1024 + lc8;            \
    const __half* gB1 = (BP) + (size_t)(n0 + lrow + 32 ) * 1024 + lc8;            \
    const unsigned sA0 = asb + (lrow      ) * RSTRIDE + (t & 7) * 16;             \
    const unsigned sA1 = asb + (lrow + 32 ) * RSTRIDE + (t & 7) * 16;             \
    const unsigned sA2 = asb + (lrow + 64 ) * RSTRIDE + (t & 7) * 16;             \
    const unsigned sA3 = asb + (lrow + 96 ) * RSTRIDE + (t & 7) * 16;             \
    const unsigned sB0 = bsb + (lrow      ) * RSTRIDE + (t & 7) * 16;             \
    const unsigned sB1 = bsb + (lrow + 32 ) * RSTRIDE + (t & 7) * 16;

#define CORE_LOAD(soff)  do {                                                     \
    cpa16(sA0 + (soff)*ASTG, gA0);  cpa16(sA1 + (soff)*ASTG, gA1);                \
    cpa16(sA2 + (soff)*ASTG, gA2);  cpa16(sA3 + (soff)*ASTG, gA3);                \
    cpa16(sB0 + (soff)*BSTG, gB0);  cpa16(sB1 + (soff)*BSTG, gB1);                \
    gA0 += 64; gA1 += 64; gA2 += 64; gA3 += 64; gB0 += 64; gB1 += 64;             \
} while(0)

#define CORE_COMPUTE(st_) do {                                                    \
    const unsigned oa = (st_) * (unsigned)ASTG;                                   \
    const unsigned ob = (st_) * (unsigned)BSTG;                                   \
    _Pragma("unroll")                                                             \
    for (int ks = 0; ks < 4; ks++) {                                              \
        const unsigned cb = ks * 32;                                              \
        unsigned a0[4], a1[4], b0[4], b1[4];                                      \
        ldm4(a0, adrA0 + oa + cb);                                                \
        ldm4(a1, adrA1 + oa + cb);                                                \
        ldm4(b0, adrB + ob + cb);                                                 \
        ldm4(b1, adrB + ob + cb + 16);                                            \
        _Pragma("unroll")                                                         \
        for (int nt = 0; nt < 4; nt++) {                                          \
            unsigned bb[2] = { b0[nt], b1[nt] };                                  \
            mma16(Co[0][nt], a0, bb);                                             \
            mma16(Co[1][nt], a1, bb);                                             \
        }                                                                         \
    }                                                                             \
} while(0)

#define CORE_MAINLOOP()                                                           \
    CORE_LOAD(0); CP_COMMIT();                                                    \
    _Pragma("unroll 2")                                                           \
    for (int kt = 0; kt < 16; kt++) {                                             \
        CP_WAIT0();                                                               \
        __syncthreads();                                                          \
        if (kt + 1 < 16) { CORE_LOAD((kt + 1) & 1); CP_COMMIT(); }                \
        CORE_COMPUTE(kt & 1);                                                     \
    }

// ---------------- fused projection GEMM + l2norm + head scatter ------------
__global__ __launch_bounds__(256, 3) void proj_gemm(
    const __half* __restrict__ A, const __half* __restrict__ Bt,
    __half* __restrict__ gq, __half* __restrict__ gk, __half* __restrict__ gv)
{
    extern __shared__ unsigned char dynsmem[];
    __shared__ float sq[128][4];

    const int t = threadIdx.x;
    const int w = t >> 5, lane = t & 31, g = lane >> 2, tig = lane & 3;
    const int wm = (w >> 1) * 32, wn = (w & 1) * 32;
    const int m0 = blockIdx.y * 128, n0 = blockIdx.x * 64;
    const int li = lane & 7, lj = lane >> 3;

    const unsigned asb = sptr(dynsmem);
    const unsigned bsb = asb + 2 * ASTG;
    const unsigned adrA0 = asb + (wm + (lj & 1) * 8 + li) * RSTRIDE + (lj >> 1) * 16;
    const unsigned adrA1 = adrA0 + 16 * RSTRIDE;
    const unsigned adrB  = bsb + (wn + lj * 8 + li) * RSTRIDE;

    CORE_DECL_LOADER(A, Bt)
    float Co[2][4][4] = {};
    CORE_MAINLOOP()

    // ---- epilogue: group sums of squares ----
    #pragma unroll
    for (int mt = 0; mt < 2; mt++) {
        float pA0 = 0, pA1 = 0, pB0 = 0, pB1 = 0;
        #pragma unroll
        for (int nt = 0; nt < 2; nt++) {
            pA0 += Co[mt][nt][0]*Co[mt][nt][0] + Co[mt][nt][1]*Co[mt][nt][1];
            pA1 += Co[mt][nt][2]*Co[mt][nt][2] + Co[mt][nt][3]*Co[mt][nt][3];
            pB0 += Co[mt][nt+2][0]*Co[mt][nt+2][0] + Co[mt][nt+2][1]*Co[mt][nt+2][1];
            pB1 += Co[mt][nt+2][2]*Co[mt][nt+2][2] + Co[mt][nt+2][3]*Co[mt][nt+2][3];
        }
        pA0 += __shfl_xor_sync(~0u, pA0, 1); pA0 += __shfl_xor_sync(~0u, pA0, 2);
        pA1 += __shfl_xor_sync(~0u, pA1, 1); pA1 += __shfl_xor_sync(~0u, pA1, 2);
        pB0 += __shfl_xor_sync(~0u, pB0, 1); pB0 += __shfl_xor_sync(~0u, pB0, 2);
        pB1 += __shfl_xor_sync(~0u, pB1, 1); pB1 += __shfl_xor_sync(~0u, pB1, 2);
        if (tig == 0) {
            int r = wm + mt * 16 + g;
            sq[r    ][2*(w&1)    ] = pA0;
            sq[r    ][2*(w&1) + 1] = pB0;
            sq[r + 8][2*(w&1)    ] = pA1;
            sq[r + 8][2*(w&1) + 1] = pB1;
        }
    }
    __syncthreads();

    const int region = (n0 < 256) ? 0 : (n0 < 512 ? 1 : 2);
    #pragma unroll
    for (int mt = 0; mt < 2; mt++)
        #pragma unroll
        for (int rh = 0; rh < 2; rh++) {
            const int r = wm + mt * 16 + g + rh * 8;
            const int m = m0 + r;
            const int b_ = m >> 11, seq = m & (SEQ - 1);
            float scv = 0.f;
            if (region == 2) {
                float ss = sq[r][0] + sq[r][1] + sq[r][2] + sq[r][3];
                scv = 1.f / fmaxf(sqrtf(ss), 1e-12f);
            }
            #pragma unroll
            for (int nt = 0; nt < 4; nt++) {
                float sc;
                if (region == 2) sc = scv;
                else {
                    int grp = 2 * (w & 1) + (nt >> 1);
                    sc = 1.f / fmaxf(sqrtf(sq[r][grp]), 1e-12f);
                }
                const int n = n0 + wn + nt * 8 + 2 * tig;
                unsigned pv = packh2(Co[mt][nt][2*rh] * sc, Co[mt][nt][2*rh+1] * sc);
                if (region == 0) {
                    int h = n >> 4, d = n & 15;
                    *(unsigned*)&gq[((size_t)(b_*NH + h) * SEQ + seq) * DKH + d] = pv;
                } else if (region == 1) {
                    int j = n - 256, h = j >> 4, d = j & 15;
                    *(unsigned*)&gk[((size_t)(b_*NH + h) * SEQ + seq) * DKH + d] = pv;
                } else {
                    int j = n - 512, h = j >> 6, d = j & 63;
                    *(unsigned*)&gv[((size_t)(b_*NH + h) * SEQ + seq) * DVH + d] = pv;
                }
            }
        }
}

// ---------------- final GEMM: C_f32[4096x1024] = A @ Bt^T (K=1024) ---------
__global__ __launch_bounds__(256, 3) void gemm_f16(
    const __half* __restrict__ A, const __half* __restrict__ Bt,
    float* __restrict__ C)
{
    extern __shared__ unsigned char dynsmem[];

    const int t = threadIdx.x;
    const int w = t >> 5, lane = t & 31, g = lane >> 2, tig = lane & 3;
    const int wm = (w >> 1) * 32, wn = (w & 1) * 32;
    const int m0 = blockIdx.y * 128, n0 = blockIdx.x * 64;
    const int li = lane & 7, lj = lane >> 3;

    const unsigned asb = sptr(dynsmem);
    const unsigned bsb = asb + 2 * ASTG;
    const unsigned adrA0 = asb + (wm + (lj & 1) * 8 + li) * RSTRIDE + (lj >> 1) * 16;
    const unsigned adrA1 = adrA0 + 16 * RSTRIDE;
    const unsigned adrB  = bsb + (wn + lj * 8 + li) * RSTRIDE;

    CORE_DECL_LOADER(A, Bt)
    float Co[2][4][4] = {};
    CORE_MAINLOOP()

    #pragma unroll
    for (int mt = 0; mt < 2; mt++)
        #pragma unroll
        for (int nt = 0; nt < 4; nt++) {
            int r = m0 + wm + mt * 16 + g;
            int c = n0 + wn + nt * 8 + 2 * tig;
            *(float2*)&C[(size_t)r * DIM + c]       = make_float2(Co[mt][nt][0], Co[mt][nt][1]);
            *(float2*)&C[(size_t)(r + 8) * DIM + c] = make_float2(Co[mt][nt][2], Co[mt][nt][3]);
        }
}

// ---------------- fused attention: register-resident S, 3 CTAs/SM ---------
// One barrier per key-tile (the top sync after WAIT0 orders buffer reuse).
#define AQS  12
#define AVSH 72
__global__ __launch_bounds__(256, 3) void attn_f16(
    const __half* __restrict__ gq, const __half* __restrict__ gk,
    const __half* __restrict__ gv, __half* __restrict__ gao)
{
    __shared__ unsigned Qs[128][AQS];
    __shared__ unsigned Ks[2][64][AQS];
    __shared__ __half   Vs[2][64][AVSH];

    const int t = threadIdx.x;
    const int w = t >> 5, lane = t & 31, g = lane >> 2, tig = lane & 3;
    const int wm = w * 16;
    const int bh = blockIdx.y, q0 = blockIdx.x * 128;
    const int li = lane & 7, lj = lane >> 3;

    const __half* qb = gq + (size_t)bh * SEQ * DKH;
    const __half* kb = gk + (size_t)bh * SEQ * DKH;
    const __half* vb = gv + (size_t)bh * SEQ * DVH;

    {
        int r = t >> 1, hf = t & 1;
        *(uint4*)&Qs[r][hf * 4] = *(const uint4*)&qb[(size_t)(q0 + r) * DKH + hf * 8];
    }

    const int kr = t >> 1, khf = t & 1;
    const int vr = t >> 3, vc = (t & 7) * 8;
    #define ATTN_LOAD(k0_, buf_) do {                                            \
        if (t < 128)                                                             \
            cpa16(sptr(&Ks[buf_][kr][khf*4]), &kb[(size_t)((k0_)+kr)*DKH + khf*8]); \
        cpa16(sptr(&Vs[buf_][vr][vc]),      &vb[(size_t)((k0_)+vr)*DVH + vc]);   \
        cpa16(sptr(&Vs[buf_][vr+32][vc]),   &vb[(size_t)((k0_)+vr+32)*DVH + vc]);\
    } while(0)

    ATTN_LOAD(0, 0);
    CP_COMMIT();
    __syncthreads();

    unsigned aq[4];
    ldm4(aq, sptr(&Qs[wm + (lj & 1) * 8 + li][(lj >> 1) * 4]));

    const unsigned KBUF = 64 * AQS * 4, VBUF = 64 * AVSH * 2;
    const unsigned adrK = sptr(&Ks[0][lj * 8 + li][0]);
    const unsigned adrV = sptr(&Vs[0][(lj & 1) * 8 + li][(lj >> 1) * 8]);

    float Co[8][4] = {};

    const int NT = SEQ / 64;
    for (int kt = 0; kt < NT; kt++) {
        CP_WAIT0();
        __syncthreads();
        if (kt + 1 < NT) { ATTN_LOAD((kt + 1) * 64, (kt + 1) & 1); CP_COMMIT(); }
        const unsigned kbase = adrK + (kt & 1) * KBUF;
        const unsigned vbase = adrV + (kt & 1) * VBUF;

        // ---- S = Q@K^T in two 32-key halves ----
        unsigned sf[4][4];
        #pragma unroll
        for (int hh = 0; hh < 2; hh++) {
            float Cs[4][4] = {};
            unsigned b0[4], b1[4];
            ldm4(b0, kbase + hh * 32 * AQS * 4);
            ldm4(b1, kbase + hh * 32 * AQS * 4 + 16);
            #pragma unroll
            for (int nt = 0; nt < 4; nt++) {
                unsigned bA[2] = { b0[nt], b1[nt] };
                mma16(Cs[nt], aq, bA);
            }
            #pragma unroll
            for (int p = 0; p < 2; p++) {
                float r0 = Cs[2*p][0];   r0 = r0 > 0.f ? r0*r0 : 0.f;
                float r1 = Cs[2*p][1];   r1 = r1 > 0.f ? r1*r1 : 0.f;
                float r2 = Cs[2*p][2];   r2 = r2 > 0.f ? r2*r2 : 0.f;
                float r3 = Cs[2*p][3];   r3 = r3 > 0.f ? r3*r3 : 0.f;
                float r4 = Cs[2*p+1][0]; r4 = r4 > 0.f ? r4*r4 : 0.f;
                float r5 = Cs[2*p+1][1]; r5 = r5 > 0.f ? r5*r5 : 0.f;
                float r6 = Cs[2*p+1][2]; r6 = r6 > 0.f ? r6*r6 : 0.f;
                float r7 = Cs[2*p+1][3]; r7 = r7 > 0.f ? r7*r7 : 0.f;
                sf[hh*2 + p][0] = packh2(r0, r1);
                sf[hh*2 + p][1] = packh2(r2, r3);
                sf[hh*2 + p][2] = packh2(r4, r5);
                sf[hh*2 + p][3] = packh2(r6, r7);
            }
        }

        // ---- Out += S @ V (4 k16 steps) ----
        #pragma unroll
        for (int ks = 0; ks < 4; ks++) {
            const unsigned vk = vbase + ks * 16 * AVSH * 2;
            #pragma unroll
            for (int j = 0; j < 4; j++) {
                unsigned vv[4];
                ldm4t(vv, vk + j * 32);
                unsigned bA[2] = { vv[0], vv[1] };
                unsigned bB[2] = { vv[2], vv[3] };
                mma16(Co[2*j],     sf[ks], bA);
                mma16(Co[2*j + 1], sf[ks], bB);
            }
        }
        // NOTE: no end-of-iter sync — the top sync of iter kt+1 (after WAIT0)
        // orders all reads of buffer kt&1 before iter kt+1 issues loads for
        // tile kt+2 into that same buffer.
    }

    float s0 = 0.f, s1 = 0.f;
    #pragma unroll
    for (int nt = 0; nt < 8; nt++) {
        s0 += Co[nt][0]*Co[nt][0] + Co[nt][1]*Co[nt][1];
        s1 += Co[nt][2]*Co[nt][2] + Co[nt][3]*Co[nt][3];
    }
    s0 += __shfl_xor_sync(~0u, s0, 1); s0 += __shfl_xor_sync(~0u, s0, 2);
    s1 += __shfl_xor_sync(~0u, s1, 1); s1 += __shfl_xor_sync(~0u, s1, 2);
    float n0s = sqrtf(s0), n1s = sqrtf(s1);
    float sc0 = tanhf(n0s) / fmaxf(n0s, 1e-12f);
    float sc1 = tanhf(n1s) / fmaxf(n1s, 1e-12f);

    const int b_ = bh >> 4, h_ = bh & 15;
    const int row0 = q0 + wm + g, row1 = row0 + 8;
    __half* d0 = gao + (size_t)(b_ * SEQ + row0) * OCOLS + h_ * DVH;
    __half* d1 = gao + (size_t)(b_ * SEQ + row1) * OCOLS + h_ * DVH;
    #pragma unroll
    for (int nt = 0; nt < 8; nt++) {
        int c = nt * 8 + 2 * tig;
        *(unsigned*)&d0[c] = packh2(Co[nt][0] * sc0, Co[nt][1] * sc0);
        *(unsigned*)&d1[c] = packh2(Co[nt][2] * sc1, Co[nt][3] * sc1);
    }
}

// ---------------- host launch ----------------
extern "C" void kernel_launch(void* const* d_in, const int* in_sizes, int n_in,
                              void* d_out, int out_size)
{
    const float *tokens = nullptr, *Wq = nullptr, *Wkv = nullptr, *Wout = nullptr;
    for (int i = 0; i < n_in; i++) {
        switch (in_sizes[i]) {
            case NTOK * DIM:   tokens = (const float*)d_in[i]; break;
            case DIM * QCOLS:  Wq     = (const float*)d_in[i]; break;
            case DIM * KVCOLS: Wkv    = (const float*)d_in[i]; break;
            case OCOLS * DIM:  Wout   = (const float*)d_in[i]; break;
        }
    }

    __half *tokh, *wc, *wot, *qn, *kn, *vh, *aoh;
    cudaGetSymbolAddress((void**)&tokh, g_tokh);
    cudaGetSymbolAddress((void**)&wc,   g_wc);
    cudaGetSymbolAddress((void**)&wot,  g_wot);
    cudaGetSymbolAddress((void**)&qn,   g_qn);
    cudaGetSymbolAddress((void**)&kn,   g_kn);
    cudaGetSymbolAddress((void**)&vh,   g_vh);
    cudaGetSymbolAddress((void**)&aoh,  g_aoh);

    cudaFuncSetAttribute(proj_gemm, cudaFuncAttributeMaxDynamicSharedMemorySize, SMEM_GEMM);
    cudaFuncSetAttribute(gemm_f16,  cudaFuncAttributeMaxDynamicSharedMemorySize, SMEM_GEMM);

    prep_all<<<PREP_TOTAL, 256>>>(tokens, Wq, Wkv, Wout, tokh, wc, wot);

    proj_gemm<<<dim3(PCOLS/64, NTOK/128), 256, SMEM_GEMM>>>(tokh, wc, qn, kn, vh);

    attn_f16<<<dim3(SEQ/128, BATCH*NH), 256>>>(qn, kn, vh, aoh);

    gemm_f16<<<dim3(DIM/64, NTOK/128), 256, SMEM_GEMM>>>(aoh, wot, (float*)d_out);
}

// round 16
// speedup vs baseline: 1.1781x; 1.0095x over previous
#include <cuda_runtime.h>
#include <cuda_fp16.h>
#include <cmath>

// Problem constants
#define BATCH   2
#define SEQ     2048
#define DIM     1024
#define NH      16
#define DKH     16
#define DVH     64
#define NTOK    (BATCH*SEQ)          // 4096
#define QCOLS   (NH*DKH)             // 256
#define KVCOLS  (NH*(DKH+DVH))       // 1280
#define OCOLS   (NH*DVH)             // 1024
#define PCOLS   1536                 // 256 q + 256 k + 1024 v (permuted)

// ---------------- scratch ----------------
__device__ __half g_tokh[NTOK * DIM];
__device__ __half g_wc  [PCOLS * DIM];
__device__ __half g_wot [DIM * OCOLS];
__device__ __half g_qn[BATCH*NH*SEQ*DKH];
__device__ __half g_kn[BATCH*NH*SEQ*DKH];
__device__ __half g_vh[BATCH*NH*SEQ*DVH];
__device__ __half g_aoh[NTOK * OCOLS];

// ---------------- helpers ----------------
__device__ __forceinline__ unsigned packh2(float a, float b){
    __half2 h = __floats2half2_rn(a, b);
    return *(unsigned*)&h;
}
__device__ __forceinline__ unsigned sptr(const void* p){
    return (unsigned)__cvta_generic_to_shared(p);
}
__device__ __forceinline__ void ldm4(unsigned r[4], unsigned a){
    asm volatile("ldmatrix.sync.aligned.m8n8.x4.shared.b16 {%0,%1,%2,%3}, [%4];"
        : "=r"(r[0]),"=r"(r[1]),"=r"(r[2]),"=r"(r[3]) : "r"(a));
}
__device__ __forceinline__ void ldm4t(unsigned r[4], unsigned a){
    asm volatile("ldmatrix.sync.aligned.m8n8.x4.trans.shared.b16 {%0,%1,%2,%3}, [%4];"
        : "=r"(r[0]),"=r"(r[1]),"=r"(r[2]),"=r"(r[3]) : "r"(a));
}
__device__ __forceinline__ void mma16(float* c, const unsigned* a, const unsigned* b){
    asm volatile("mma.sync.aligned.m16n8k16.row.col.f32.f16.f16.f32 "
        "{%0,%1,%2,%3},{%4,%5,%6,%7},{%8,%9},{%0,%1,%2,%3};\n"
        : "+f"(c[0]),"+f"(c[1]),"+f"(c[2]),"+f"(c[3])
        : "r"(a[0]),"r"(a[1]),"r"(a[2]),"r"(a[3]),"r"(b[0]),"r"(b[1]));
}
__device__ __forceinline__ void cpa16(unsigned dst, const void* src){
    asm volatile("cp.async.cg.shared.global [%0], [%1], 16;" :: "r"(dst), "l"(src));
}
#define CP_COMMIT() asm volatile("cp.async.commit_group;" ::: "memory")
#define CP_WAIT0()  asm volatile("cp.async.wait_group 0;" ::: "memory")

// ---------------- fused prep kernel ----------------
#define PREP_CVT_BLOCKS   2048
#define PREP_WPREP_BLOCKS 1536
#define PREP_WT_BLOCKS    1024
#define PREP_TOTAL (PREP_CVT_BLOCKS + PREP_WPREP_BLOCKS + PREP_WT_BLOCKS)

__global__ __launch_bounds__(256) void prep_all(
    const float* __restrict__ tokens, const float* __restrict__ Wq,
    const float* __restrict__ Wkv, const float* __restrict__ Wout,
    __half* __restrict__ tokh, __half* __restrict__ Wc, __half* __restrict__ Wt)
{
    __shared__ float ts[32][33];
    const int bid = blockIdx.x;
    const int t = threadIdx.x;

    if (bid < PREP_CVT_BLOCKS) {
        int i = bid * 256 + t;
        float4 a = ((const float4*)tokens)[2*i];
        float4 b = ((const float4*)tokens)[2*i+1];
        uint4 p = make_uint4(packh2(a.x,a.y), packh2(a.z,a.w),
                             packh2(b.x,b.y), packh2(b.z,b.w));
        ((uint4*)tokh)[i] = p;
    } else if (bid < PREP_CVT_BLOCKS + PREP_WPREP_BLOCKS) {
        int jb = bid - PREP_CVT_BLOCKS;
        const int n0 = (jb % 48) * 32, k0 = (jb / 48) * 32;
        const int tx = t & 31, ty = t >> 5;
        {
            const int n = n0 + tx;
            const float* W; int c, ld;
            if (n < 256)      { W = Wq;  ld = QCOLS;  c = n; }
            else if (n < 512) { int j = n - 256; W = Wkv; ld = KVCOLS; c = (j >> 4) * 80 + (j & 15); }
            else              { int j = n - 512; W = Wkv; ld = KVCOLS; c = (j >> 6) * 80 + 16 + (j & 63); }
            #pragma unroll
            for (int i = 0; i < 32; i += 8)
                ts[ty + i][tx] = W[(size_t)(k0 + ty + i) * ld + c];
        }
        __syncthreads();
        #pragma unroll
        for (int i = 0; i < 32; i += 8)
            Wc[(size_t)(n0 + ty + i) * DIM + k0 + tx] = __float2half(ts[tx][ty + i]);
    } else {
        int jb = bid - PREP_CVT_BLOCKS - PREP_WPREP_BLOCKS;
        const int n0 = (jb % 32) * 32, k0 = (jb / 32) * 32;
        const int tx = t & 31, ty = t >> 5;
        #pragma unroll
        for (int i = 0; i < 32; i += 8)
            ts[ty + i][tx] = Wout[(size_t)(k0 + ty + i) * DIM + n0 + tx];
        __syncthreads();
        #pragma unroll
        for (int i = 0; i < 32; i += 8)
            Wt[(size_t)(n0 + ty + i) * OCOLS + k0 + tx] = __float2half(ts[tx][ty + i]);
    }
}

// ====== GEMM core: 128x64 block, 8 warps, warp 32x32, BK=64, 2 stages =====
#define RSTRIDE 144
#define ASTG (128 * RSTRIDE)
#define BSTG (64 * RSTRIDE)
#define SMEM_GEMM (2 * (ASTG + BSTG))   // 55296 B

#define CORE_DECL_LOADER(AP, BP)                                                  \
    const int lrow = t >> 3, lc8 = (t & 7) * 8;                                   \
    const __half* gA0 = (AP) + (size_t)(m0 + lrow      ) * 1024 + lc8;            \
    const __half* gA1 = (AP) + (size_t)(m0 + lrow + 32 ) * 1024 + lc8;            \
    const __half* gA2 = (AP) + (size_t)(m0 + lrow + 64 ) * 1024 + lc8;            \
    const __half* gA3 = (AP) + (size_t)(m0 + lrow + 96 ) * 1024 + lc8;            \
    const __half* gB0 = (BP) + (size_t)(n0 + lrow      ) * 1024 + lc8;            \
    const __half* gB1 = (BP) + (size_t)(n0 + lrow + 32 ) * 1024 + lc8;            \
    const unsigned sA0 = asb + (lrow      ) * RSTRIDE + (t & 7) * 16;             \
    const unsigned sA1 = asb + (lrow + 32 ) * RSTRIDE + (t & 7) * 16;             \
    const unsigned sA2 = asb + (lrow + 64 ) * RSTRIDE + (t & 7) * 16;             \
    const unsigned sA3 = asb + (lrow + 96 ) * RSTRIDE + (t & 7) * 16;             \
    const unsigned sB0 = bsb + (lrow      ) * RSTRIDE + (t & 7) * 16;             \
    const unsigned sB1 = bsb + (lrow + 32 ) * RSTRIDE + (t & 7) * 16;

#define CORE_LOAD(soff)  do {                                                     \
    cpa16(sA0 + (soff)*ASTG, gA0);  cpa16(sA1 + (soff)*ASTG, gA1);                \
    cpa16(sA2 + (soff)*ASTG, gA2);  cpa16(sA3 + (soff)*ASTG, gA3);                \
    cpa16(sB0 + (soff)*BSTG, gB0);  cpa16(sB1 + (soff)*BSTG, gB1);                \
    gA0 += 64; gA1 += 64; gA2 += 64; gA3 += 64; gB0 += 64; gB1 += 64;             \
} while(0)

#define CORE_COMPUTE(st_) do {                                                    \
    const unsigned oa = (st_) * (unsigned)ASTG;                                   \
    const unsigned ob = (st_) * (unsigned)BSTG;                                   \
    _Pragma("unroll")                                                             \
    for (int ks = 0; ks < 4; ks++) {                                              \
        const unsigned cb = ks * 32;                                              \
        unsigned a0[4], a1[4], b0[4], b1[4];                                      \
        ldm4(a0, adrA0 + oa + cb);                                                \
        ldm4(a1, adrA1 + oa + cb);                                                \
        ldm4(b0, adrB + ob + cb);                                                 \
        ldm4(b1, adrB + ob + cb + 16);                                            \
        _Pragma("unroll")                                                         \
        for (int nt = 0; nt < 4; nt++) {                                          \
            unsigned bb[2] = { b0[nt], b1[nt] };                                  \
            mma16(Co[0][nt], a0, bb);                                             \
            mma16(Co[1][nt], a1, bb);                                             \
        }                                                                         \
    }                                                                             \
} while(0)

#define CORE_MAINLOOP()                                                           \
    CORE_LOAD(0); CP_COMMIT();                                                    \
    _Pragma("unroll 2")                                                           \
    for (int kt = 0; kt < 16; kt++) {                                             \
        CP_WAIT0();                                                               \
        __syncthreads();                                                          \
        if (kt + 1 < 16) { CORE_LOAD((kt + 1) & 1); CP_COMMIT(); }                \
        CORE_COMPUTE(kt & 1);                                                     \
    }

// ---------------- fused projection GEMM + l2norm + head scatter ------------
__global__ __launch_bounds__(256, 3) void proj_gemm(
    const __half* __restrict__ A, const __half* __restrict__ Bt,
    __half* __restrict__ gq, __half* __restrict__ gk, __half* __restrict__ gv)
{
    extern __shared__ unsigned char dynsmem[];
    __shared__ float sq[128][4];

    const int t = threadIdx.x;
    const int w = t >> 5, lane = t & 31, g = lane >> 2, tig = lane & 3;
    const int wm = (w >> 1) * 32, wn = (w & 1) * 32;
    const int m0 = blockIdx.y * 128, n0 = blockIdx.x * 64;
    const int li = lane & 7, lj = lane >> 3;

    const unsigned asb = sptr(dynsmem);
    const unsigned bsb = asb + 2 * ASTG;
    const unsigned adrA0 = asb + (wm + (lj & 1) * 8 + li) * RSTRIDE + (lj >> 1) * 16;
    const unsigned adrA1 = adrA0 + 16 * RSTRIDE;
    const unsigned adrB  = bsb + (wn + lj * 8 + li) * RSTRIDE;

    CORE_DECL_LOADER(A, Bt)
    float Co[2][4][4] = {};
    CORE_MAINLOOP()

    #pragma unroll
    for (int mt = 0; mt < 2; mt++) {
        float pA0 = 0, pA1 = 0, pB0 = 0, pB1 = 0;
        #pragma unroll
        for (int nt = 0; nt < 2; nt++) {
            pA0 += Co[mt][nt][0]*Co[mt][nt][0] + Co[mt][nt][1]*Co[mt][nt][1];
            pA1 += Co[mt][nt][2]*Co[mt][nt][2] + Co[mt][nt][3]*Co[mt][nt][3];
            pB0 += Co[mt][nt+2][0]*Co[mt][nt+2][0] + Co[mt][nt+2][1]*Co[mt][nt+2][1];
            pB1 += Co[mt][nt+2][2]*Co[mt][nt+2][2] + Co[mt][nt+2][3]*Co[mt][nt+2][3];
        }
        pA0 += __shfl_xor_sync(~0u, pA0, 1); pA0 += __shfl_xor_sync(~0u, pA0, 2);
        pA1 += __shfl_xor_sync(~0u, pA1, 1); pA1 += __shfl_xor_sync(~0u, pA1, 2);
        pB0 += __shfl_xor_sync(~0u, pB0, 1); pB0 += __shfl_xor_sync(~0u, pB0, 2);
        pB1 += __shfl_xor_sync(~0u, pB1, 1); pB1 += __shfl_xor_sync(~0u, pB1, 2);
        if (tig == 0) {
            int r = wm + mt * 16 + g;
            sq[r    ][2*(w&1)    ] = pA0;
            sq[r    ][2*(w&1) + 1] = pB0;
            sq[r + 8][2*(w&1)    ] = pA1;
            sq[r + 8][2*(w&1) + 1] = pB1;
        }
    }
    __syncthreads();

    const int region = (n0 < 256) ? 0 : (n0 < 512 ? 1 : 2);
    #pragma unroll
    for (int mt = 0; mt < 2; mt++)
        #pragma unroll
        for (int rh = 0; rh < 2; rh++) {
            const int r = wm + mt * 16 + g + rh * 8;
            const int m = m0 + r;
            const int b_ = m >> 11, seq = m & (SEQ - 1);
            float scv = 0.f;
            if (region == 2) {
                float ss = sq[r][0] + sq[r][1] + sq[r][2] + sq[r][3];
                scv = 1.f / fmaxf(sqrtf(ss), 1e-12f);
            }
            #pragma unroll
            for (int nt = 0; nt < 4; nt++) {
                float sc;
                if (region == 2) sc = scv;
                else {
                    int grp = 2 * (w & 1) + (nt >> 1);
                    sc = 1.f / fmaxf(sqrtf(sq[r][grp]), 1e-12f);
                }
                const int n = n0 + wn + nt * 8 + 2 * tig;
                unsigned pv = packh2(Co[mt][nt][2*rh] * sc, Co[mt][nt][2*rh+1] * sc);
                if (region == 0) {
                    int h = n >> 4, d = n & 15;
                    *(unsigned*)&gq[((size_t)(b_*NH + h) * SEQ + seq) * DKH + d] = pv;
                } else if (region == 1) {
                    int j = n - 256, h = j >> 4, d = j & 15;
                    *(unsigned*)&gk[((size_t)(b_*NH + h) * SEQ + seq) * DKH + d] = pv;
                } else {
                    int j = n - 512, h = j >> 6, d = j & 63;
                    *(unsigned*)&gv[((size_t)(b_*NH + h) * SEQ + seq) * DVH + d] = pv;
                }
            }
        }
}

// ---------------- final GEMM: C_f32[4096x1024] = A @ Bt^T (K=1024) ---------
__global__ __launch_bounds__(256, 3) void gemm_f16(
    const __half* __restrict__ A, const __half* __restrict__ Bt,
    float* __restrict__ C)
{
    extern __shared__ unsigned char dynsmem[];

    const int t = threadIdx.x;
    const int w = t >> 5, lane = t & 31, g = lane >> 2, tig = lane & 3;
    const int wm = (w >> 1) * 32, wn = (w & 1) * 32;
    const int m0 = blockIdx.y * 128, n0 = blockIdx.x * 64;
    const int li = lane & 7, lj = lane >> 3;

    const unsigned asb = sptr(dynsmem);
    const unsigned bsb = asb + 2 * ASTG;
    const unsigned adrA0 = asb + (wm + (lj & 1) * 8 + li) * RSTRIDE + (lj >> 1) * 16;
    const unsigned adrA1 = adrA0 + 16 * RSTRIDE;
    const unsigned adrB  = bsb + (wn + lj * 8 + li) * RSTRIDE;

    CORE_DECL_LOADER(A, Bt)
    float Co[2][4][4] = {};
    CORE_MAINLOOP()

    #pragma unroll
    for (int mt = 0; mt < 2; mt++)
        #pragma unroll
        for (int nt = 0; nt < 4; nt++) {
            int r = m0 + wm + mt * 16 + g;
            int c = n0 + wn + nt * 8 + 2 * tig;
            *(float2*)&C[(size_t)r * DIM + c]       = make_float2(Co[mt][nt][0], Co[mt][nt][1]);
            *(float2*)&C[(size_t)(r + 8) * DIM + c] = make_float2(Co[mt][nt][2], Co[mt][nt][3]);
        }
}

// ---------------- fused attention: 64-query CTAs, 128 threads, 4 warps -----
#define AQS  12
#define AVSH 72
__global__ __launch_bounds__(128, 5) void attn_f16(
    const __half* __restrict__ gq, const __half* __restrict__ gk,
    const __half* __restrict__ gv, __half* __restrict__ gao)
{
    __shared__ unsigned Qs[64][AQS];
    __shared__ unsigned Ks[2][64][AQS];
    __shared__ __half   Vs[2][64][AVSH];

    const int t = threadIdx.x;
    const int w = t >> 5, lane = t & 31, g = lane >> 2, tig = lane & 3;
    const int wm = w * 16;
    const int bh = blockIdx.y, q0 = blockIdx.x * 64;
    const int li = lane & 7, lj = lane >> 3;

    const __half* qb = gq + (size_t)bh * SEQ * DKH;
    const __half* kb = gk + (size_t)bh * SEQ * DKH;
    const __half* vb = gv + (size_t)bh * SEQ * DVH;

    // Q tile 64x16: 128 uint4, one per thread
    {
        int r = t >> 1, hf = t & 1;
        *(uint4*)&Qs[r][hf * 4] = *(const uint4*)&qb[(size_t)(q0 + r) * DKH + hf * 8];
    }

    const int kr = t >> 1, khf = t & 1;
    #define ATTN_LOAD(k0_, buf_) do {                                            \
        cpa16(sptr(&Ks[buf_][kr][khf*4]), &kb[(size_t)((k0_)+kr)*DKH + khf*8]);  \
        _Pragma("unroll")                                                        \
        for (int i_ = 0; i_ < 4; i_++) {                                         \
            int idx_ = t + i_ * 128;                                             \
            int r_ = idx_ >> 3, c_ = (idx_ & 7) * 8;                             \
            cpa16(sptr(&Vs[buf_][r_][c_]), &vb[(size_t)((k0_)+r_)*DVH + c_]);    \
        }                                                                        \
    } while(0)

    ATTN_LOAD(0, 0);
    CP_COMMIT();
    __syncthreads();

    unsigned aq[4];
    ldm4(aq, sptr(&Qs[wm + (lj & 1) * 8 + li][(lj >> 1) * 4]));

    const unsigned KBUF = 64 * AQS * 4, VBUF = 64 * AVSH * 2;
    const unsigned adrK = sptr(&Ks[0][lj * 8 + li][0]);
    const unsigned adrV = sptr(&Vs[0][(lj & 1) * 8 + li][(lj >> 1) * 8]);

    float Co[8][4] = {};

    const int NT = SEQ / 64;
    for (int kt = 0; kt < NT; kt++) {
        CP_WAIT0();
        __syncthreads();
        if (kt + 1 < NT) { ATTN_LOAD((kt + 1) * 64, (kt + 1) & 1); CP_COMMIT(); }
        const unsigned kbase = adrK + (kt & 1) * KBUF;
        const unsigned vbase = adrV + (kt & 1) * VBUF;

        // ---- S = Q@K^T in two 32-key halves ----
        unsigned sf[4][4];
        #pragma unroll
        for (int hh = 0; hh < 2; hh++) {
            float Cs[4][4] = {};
            unsigned b0[4], b1[4];
            ldm4(b0, kbase + hh * 32 * AQS * 4);
            ldm4(b1, kbase + hh * 32 * AQS * 4 + 16);
            #pragma unroll
            for (int nt = 0; nt < 4; nt++) {
                unsigned bA[2] = { b0[nt], b1[nt] };
                mma16(Cs[nt], aq, bA);
            }
            #pragma unroll
            for (int p = 0; p < 2; p++) {
                float r0 = Cs[2*p][0];   r0 = r0 > 0.f ? r0*r0 : 0.f;
                float r1 = Cs[2*p][1];   r1 = r1 > 0.f ? r1*r1 : 0.f;
                float r2 = Cs[2*p][2];   r2 = r2 > 0.f ? r2*r2 : 0.f;
                float r3 = Cs[2*p][3];   r3 = r3 > 0.f ? r3*r3 : 0.f;
                float r4 = Cs[2*p+1][0]; r4 = r4 > 0.f ? r4*r4 : 0.f;
                float r5 = Cs[2*p+1][1]; r5 = r5 > 0.f ? r5*r5 : 0.f;
                float r6 = Cs[2*p+1][2]; r6 = r6 > 0.f ? r6*r6 : 0.f;
                float r7 = Cs[2*p+1][3]; r7 = r7 > 0.f ? r7*r7 : 0.f;
                sf[hh*2 + p][0] = packh2(r0, r1);
                sf[hh*2 + p][1] = packh2(r2, r3);
                sf[hh*2 + p][2] = packh2(r4, r5);
                sf[hh*2 + p][3] = packh2(r6, r7);
            }
        }

        // ---- Out += S @ V (4 k16 steps) ----
        #pragma unroll
        for (int ks = 0; ks < 4; ks++) {
            const unsigned vk = vbase + ks * 16 * AVSH * 2;
            #pragma unroll
            for (int j = 0; j < 4; j++) {
                unsigned vv[4];
                ldm4t(vv, vk + j * 32);
                unsigned bA[2] = { vv[0], vv[1] };
                unsigned bB[2] = { vv[2], vv[3] };
                mma16(Co[2*j],     sf[ks], bA);
                mma16(Co[2*j + 1], sf[ks], bB);
            }
        }
        // no end-of-iter sync (top sync of next iter orders buffer reuse)
    }

    float s0 = 0.f, s1 = 0.f;
    #pragma unroll
    for (int nt = 0; nt < 8; nt++) {
        s0 += Co[nt][0]*Co[nt][0] + Co[nt][1]*Co[nt][1];
        s1 += Co[nt][2]*Co[nt][2] + Co[nt][3]*Co[nt][3];
    }
    s0 += __shfl_xor_sync(~0u, s0, 1); s0 += __shfl_xor_sync(~0u, s0, 2);
    s1 += __shfl_xor_sync(~0u, s1, 1); s1 += __shfl_xor_sync(~0u, s1, 2);
    float n0s = sqrtf(s0), n1s = sqrtf(s1);
    float sc0 = tanhf(n0s) / fmaxf(n0s, 1e-12f);
    float sc1 = tanhf(n1s) / fmaxf(n1s, 1e-12f);

    const int b_ = bh >> 4, h_ = bh & 15;
    const int row0 = q0 + wm + g, row1 = row0 + 8;
    __half* d0 = gao + (size_t)(b_ * SEQ + row0) * OCOLS + h_ * DVH;
    __half* d1 = gao + (size_t)(b_ * SEQ + row1) * OCOLS + h_ * DVH;
    #pragma unroll
    for (int nt = 0; nt < 8; nt++) {
        int c = nt * 8 + 2 * tig;
        *(unsigned*)&d0[c] = packh2(Co[nt][0] * sc0, Co[nt][1] * sc0);
        *(unsigned*)&d1[c] = packh2(Co[nt][2] * sc1, Co[nt][3] * sc1);
    }
}

// ---------------- host launch ----------------
extern "C" void kernel_launch(void* const* d_in, const int* in_sizes, int n_in,
                              void* d_out, int out_size)
{
    const float *tokens = nullptr, *Wq = nullptr, *Wkv = nullptr, *Wout = nullptr;
    for (int i = 0; i < n_in; i++) {
        switch (in_sizes[i]) {
            case NTOK * DIM:   tokens = (const float*)d_in[i]; break;
            case DIM * QCOLS:  Wq     = (const float*)d_in[i]; break;
            case DIM * KVCOLS: Wkv    = (const float*)d_in[i]; break;
            case OCOLS * DIM:  Wout   = (const float*)d_in[i]; break;
        }
    }

    __half *tokh, *wc, *wot, *qn, *kn, *vh, *aoh;
    cudaGetSymbolAddress((void**)&tokh, g_tokh);
    cudaGetSymbolAddress((void**)&wc,   g_wc);
    cudaGetSymbolAddress((void**)&wot,  g_wot);
    cudaGetSymbolAddress((void**)&qn,   g_qn);
    cudaGetSymbolAddress((void**)&kn,   g_kn);
    cudaGetSymbolAddress((void**)&vh,   g_vh);
    cudaGetSymbolAddress((void**)&aoh,  g_aoh);

    cudaFuncSetAttribute(proj_gemm, cudaFuncAttributeMaxDynamicSharedMemorySize, SMEM_GEMM);
    cudaFuncSetAttribute(gemm_f16,  cudaFuncAttributeMaxDynamicSharedMemorySize, SMEM_GEMM);

    prep_all<<<PREP_TOTAL, 256>>>(tokens, Wq, Wkv, Wout, tokh, wc, wot);

    proj_gemm<<<dim3(PCOLS/64, NTOK/128), 256, SMEM_GEMM>>>(tokh, wc, qn, kn, vh);

    attn_f16<<<dim3(SEQ/64, BATCH*NH), 128>>>(qn, kn, vh, aoh);

    gemm_f16<<<dim3(DIM/64, NTOK/128), 256, SMEM_GEMM>>>(aoh, wot, (float*)d_out);
}

// round 17
// speedup vs baseline: 1.1823x; 1.0035x over previous
#include <cuda_runtime.h>
#include <cuda_fp16.h>
#include <cmath>

// Problem constants
#define BATCH   2
#define SEQ     2048
#define DIM     1024
#define NH      16
#define DKH     16
#define DVH     64
#define NTOK    (BATCH*SEQ)          // 4096
#define QCOLS   (NH*DKH)             // 256
#define KVCOLS  (NH*(DKH+DVH))       // 1280
#define OCOLS   (NH*DVH)             // 1024
#define PCOLS   1536                 // 256 q + 256 k + 1024 v (permuted)

// ---------------- scratch ----------------
__device__ __half g_tokh[NTOK * DIM];
__device__ __half g_wc  [PCOLS * DIM];
__device__ __half g_wot [DIM * OCOLS];
__device__ __half g_qn[BATCH*NH*SEQ*DKH];
__device__ __half g_kn[BATCH*NH*SEQ*DKH];
__device__ __half g_vh[BATCH*NH*SEQ*DVH];
__device__ __half g_aoh[NTOK * OCOLS];

// ---------------- helpers ----------------
__device__ __forceinline__ unsigned packh2(float a, float b){
    __half2 h = __floats2half2_rn(a, b);
    return *(unsigned*)&h;
}
__device__ __forceinline__ unsigned sptr(const void* p){
    return (unsigned)__cvta_generic_to_shared(p);
}
__device__ __forceinline__ void ldm4(unsigned r[4], unsigned a){
    asm volatile("ldmatrix.sync.aligned.m8n8.x4.shared.b16 {%0,%1,%2,%3}, [%4];"
        : "=r"(r[0]),"=r"(r[1]),"=r"(r[2]),"=r"(r[3]) : "r"(a));
}
__device__ __forceinline__ void ldm4t(unsigned r[4], unsigned a){
    asm volatile("ldmatrix.sync.aligned.m8n8.x4.trans.shared.b16 {%0,%1,%2,%3}, [%4];"
        : "=r"(r[0]),"=r"(r[1]),"=r"(r[2]),"=r"(r[3]) : "r"(a));
}
__device__ __forceinline__ void mma16(float* c, const unsigned* a, const unsigned* b){
    asm volatile("mma.sync.aligned.m16n8k16.row.col.f32.f16.f16.f32 "
        "{%0,%1,%2,%3},{%4,%5,%6,%7},{%8,%9},{%0,%1,%2,%3};\n"
        : "+f"(c[0]),"+f"(c[1]),"+f"(c[2]),"+f"(c[3])
        : "r"(a[0]),"r"(a[1]),"r"(a[2]),"r"(a[3]),"r"(b[0]),"r"(b[1]));
}
__device__ __forceinline__ void cpa16(unsigned dst, const void* src){
    asm volatile("cp.async.cg.shared.global [%0], [%1], 16;" :: "r"(dst), "l"(src));
}
#define CP_COMMIT() asm volatile("cp.async.commit_group;" ::: "memory")
#define CP_WAIT0()  asm volatile("cp.async.wait_group 0;" ::: "memory")

// ---------------- fused prep kernel ----------------
#define PREP_CVT_BLOCKS   2048
#define PREP_WPREP_BLOCKS 1536
#define PREP_WT_BLOCKS    1024
#define PREP_TOTAL (PREP_CVT_BLOCKS + PREP_WPREP_BLOCKS + PREP_WT_BLOCKS)

__global__ __launch_bounds__(256) void prep_all(
    const float* __restrict__ tokens, const float* __restrict__ Wq,
    const float* __restrict__ Wkv, const float* __restrict__ Wout,
    __half* __restrict__ tokh, __half* __restrict__ Wc, __half* __restrict__ Wt)
{
    __shared__ float ts[32][33];
    const int bid = blockIdx.x;
    const int t = threadIdx.x;

    if (bid < PREP_CVT_BLOCKS) {
        int i = bid * 256 + t;
        float4 a = ((const float4*)tokens)[2*i];
        float4 b = ((const float4*)tokens)[2*i+1];
        uint4 p = make_uint4(packh2(a.x,a.y), packh2(a.z,a.w),
                             packh2(b.x,b.y), packh2(b.z,b.w));
        ((uint4*)tokh)[i] = p;
    } else if (bid < PREP_CVT_BLOCKS + PREP_WPREP_BLOCKS) {
        int jb = bid - PREP_CVT_BLOCKS;
        const int n0 = (jb % 48) * 32, k0 = (jb / 48) * 32;
        const int tx = t & 31, ty = t >> 5;
        {
            const int n = n0 + tx;
            const float* W; int c, ld;
            if (n < 256)      { W = Wq;  ld = QCOLS;  c = n; }
            else if (n < 512) { int j = n - 256; W = Wkv; ld = KVCOLS; c = (j >> 4) * 80 + (j & 15); }
            else              { int j = n - 512; W = Wkv; ld = KVCOLS; c = (j >> 6) * 80 + 16 + (j & 63); }
            #pragma unroll
            for (int i = 0; i < 32; i += 8)
                ts[ty + i][tx] = W[(size_t)(k0 + ty + i) * ld + c];
        }
        __syncthreads();
        #pragma unroll
        for (int i = 0; i < 32; i += 8)
            Wc[(size_t)(n0 + ty + i) * DIM + k0 + tx] = __float2half(ts[tx][ty + i]);
    } else {
        int jb = bid - PREP_CVT_BLOCKS - PREP_WPREP_BLOCKS;
        const int n0 = (jb % 32) * 32, k0 = (jb / 32) * 32;
        const int tx = t & 31, ty = t >> 5;
        #pragma unroll
        for (int i = 0; i < 32; i += 8)
            ts[ty + i][tx] = Wout[(size_t)(k0 + ty + i) * DIM + n0 + tx];
        __syncthreads();
        #pragma unroll
        for (int i = 0; i < 32; i += 8)
            Wt[(size_t)(n0 + ty + i) * OCOLS + k0 + tx] = __float2half(ts[tx][ty + i]);
    }
}

// ====== GEMM core: 64x64 block, 128 threads (4 warps, warp 32x32), =========
// BK=64, 2 stages, 6 CTAs/SM. Per-warp stream identical to R16 (32 MMA/iter).
#define RSTRIDE 144
#define STG64 (64 * RSTRIDE)            // 9216 B per stage per array
// static smem layout: [A st0][A st1][B st0][B st1] = 4*STG64 = 36864 B

#define G64_DECL(AP, BP)                                                          \
    const int lr = t >> 3;                                                        \
    const __half* gA = (AP) + (size_t)(m0 + lr) * 1024 + (t & 7) * 8;             \
    const __half* gB = (BP) + (size_t)(n0 + lr) * 1024 + (t & 7) * 8;             \
    const unsigned sA = asb + lr * RSTRIDE + (t & 7) * 16;                        \
    const unsigned sB = bsb + lr * RSTRIDE + (t & 7) * 16;

#define G64_LOAD(soff)  do {                                                      \
    cpa16(sA + (soff)*STG64,                   gA);                               \
    cpa16(sA + (soff)*STG64 + 16*RSTRIDE,      gA + 16*1024);                     \
    cpa16(sA + (soff)*STG64 + 32*RSTRIDE,      gA + 32*1024);                     \
    cpa16(sA + (soff)*STG64 + 48*RSTRIDE,      gA + 48*1024);                     \
    cpa16(sB + (soff)*STG64,                   gB);                               \
    cpa16(sB + (soff)*STG64 + 16*RSTRIDE,      gB + 16*1024);                     \
    cpa16(sB + (soff)*STG64 + 32*RSTRIDE,      gB + 32*1024);                     \
    cpa16(sB + (soff)*STG64 + 48*RSTRIDE,      gB + 48*1024);                     \
    gA += 64; gB += 64;                                                           \
} while(0)

#define G64_COMPUTE(st_) do {                                                     \
    const unsigned oo = (st_) * (unsigned)STG64;                                  \
    _Pragma("unroll")                                                             \
    for (int ks = 0; ks < 4; ks++) {                                              \
        const unsigned cb = ks * 32;                                              \
        unsigned a0[4], a1[4], b0[4], b1[4];                                      \
        ldm4(a0, adrA0 + oo + cb);                                                \
        ldm4(a1, adrA1 + oo + cb);                                                \
        ldm4(b0, adrB + oo + cb);                                                 \
        ldm4(b1, adrB + oo + cb + 16);                                            \
        _Pragma("unroll")                                                         \
        for (int nt = 0; nt < 4; nt++) {                                          \
            unsigned bb[2] = { b0[nt], b1[nt] };                                  \
            mma16(Co[0][nt], a0, bb);                                             \
            mma16(Co[1][nt], a1, bb);                                             \
        }                                                                         \
    }                                                                             \
} while(0)

#define G64_MAINLOOP()                                                            \
    G64_LOAD(0); CP_COMMIT();                                                     \
    _Pragma("unroll 2")                                                           \
    for (int kt = 0; kt < 16; kt++) {                                             \
        CP_WAIT0();                                                               \
        __syncthreads();                                                          \
        if (kt + 1 < 16) { G64_LOAD((kt + 1) & 1); CP_COMMIT(); }                 \
        G64_COMPUTE(kt & 1);                                                      \
    }

// ---------------- fused projection GEMM + l2norm + head scatter ------------
__global__ __launch_bounds__(128, 6) void proj_gemm(
    const __half* __restrict__ A, const __half* __restrict__ Bt,
    __half* __restrict__ gq, __half* __restrict__ gk, __half* __restrict__ gv)
{
    __shared__ __align__(16) unsigned char tiles[4 * STG64];
    float (*sq)[4] = (float(*)[4])tiles;     // overlays stage-0 A after mainloop

    const int t = threadIdx.x;
    const int w = t >> 5, lane = t & 31, g = lane >> 2, tig = lane & 3;
    const int wm = (w >> 1) * 32, wn = (w & 1) * 32;
    const int m0 = blockIdx.y * 64, n0 = blockIdx.x * 64;
    const int li = lane & 7, lj = lane >> 3;

    const unsigned asb = sptr(tiles);
    const unsigned bsb = asb + 2 * STG64;
    const unsigned adrA0 = asb + (wm + (lj & 1) * 8 + li) * RSTRIDE + (lj >> 1) * 16;
    const unsigned adrA1 = adrA0 + 16 * RSTRIDE;
    const unsigned adrB  = bsb + (wn + lj * 8 + li) * RSTRIDE;

    G64_DECL(A, Bt)
    float Co[2][4][4] = {};
    G64_MAINLOOP()

    // ---- epilogue: group sums of squares (sq overlays free tile smem) ----
    // Last compute read stage 1; sq occupies stage-0 A region. Each warp
    // writes only its own (row, col-group) cells; barrier before reads.
    #pragma unroll
    for (int mt = 0; mt < 2; mt++) {
        float pA0 = 0, pA1 = 0, pB0 = 0, pB1 = 0;
        #pragma unroll
        for (int nt = 0; nt < 2; nt++) {
            pA0 += Co[mt][nt][0]*Co[mt][nt][0] + Co[mt][nt][1]*Co[mt][nt][1];
            pA1 += Co[mt][nt][2]*Co[mt][nt][2] + Co[mt][nt][3]*Co[mt][nt][3];
            pB0 += Co[mt][nt+2][0]*Co[mt][nt+2][0] + Co[mt][nt+2][1]*Co[mt][nt+2][1];
            pB1 += Co[mt][nt+2][2]*Co[mt][nt+2][2] + Co[mt][nt+2][3]*Co[mt][nt+2][3];
        }
        pA0 += __shfl_xor_sync(~0u, pA0, 1); pA0 += __shfl_xor_sync(~0u, pA0, 2);
        pA1 += __shfl_xor_sync(~0u, pA1, 1); pA1 += __shfl_xor_sync(~0u, pA1, 2);
        pB0 += __shfl_xor_sync(~0u, pB0, 1); pB0 += __shfl_xor_sync(~0u, pB0, 2);
        pB1 += __shfl_xor_sync(~0u, pB1, 1); pB1 += __shfl_xor_sync(~0u, pB1, 2);
        if (tig == 0) {
            int r = wm + mt * 16 + g;
            sq[r    ][2*(w&1)    ] = pA0;
            sq[r    ][2*(w&1) + 1] = pB0;
            sq[r + 8][2*(w&1)    ] = pA1;
            sq[r + 8][2*(w&1) + 1] = pB1;
        }
    }
    __syncthreads();

    const int region = (n0 < 256) ? 0 : (n0 < 512 ? 1 : 2);
    #pragma unroll
    for (int mt = 0; mt < 2; mt++)
        #pragma unroll
        for (int rh = 0; rh < 2; rh++) {
            const int r = wm + mt * 16 + g + rh * 8;
            const int m = m0 + r;
            const int b_ = m >> 11, seq = m & (SEQ - 1);
            float scv = 0.f;
            if (region == 2) {
                float ss = sq[r][0] + sq[r][1] + sq[r][2] + sq[r][3];
                scv = 1.f / fmaxf(sqrtf(ss), 1e-12f);
            }
            #pragma unroll
            for (int nt = 0; nt < 4; nt++) {
                float sc;
                if (region == 2) sc = scv;
                else {
                    int grp = 2 * (w & 1) + (nt >> 1);
                    sc = 1.f / fmaxf(sqrtf(sq[r][grp]), 1e-12f);
                }
                const int n = n0 + wn + nt * 8 + 2 * tig;
                unsigned pv = packh2(Co[mt][nt][2*rh] * sc, Co[mt][nt][2*rh+1] * sc);
                if (region == 0) {
                    int h = n >> 4, d = n & 15;
                    *(unsigned*)&gq[((size_t)(b_*NH + h) * SEQ + seq) * DKH + d] = pv;
                } else if (region == 1) {
                    int j = n - 256, h = j >> 4, d = j & 15;
                    *(unsigned*)&gk[((size_t)(b_*NH + h) * SEQ + seq) * DKH + d] = pv;
                } else {
                    int j = n - 512, h = j >> 6, d = j & 63;
                    *(unsigned*)&gv[((size_t)(b_*NH + h) * SEQ + seq) * DVH + d] = pv;
                }
            }
        }
}

// ---------------- final GEMM: C_f32[4096x1024] = A @ Bt^T (K=1024) ---------
__global__ __launch_bounds__(128, 6) void gemm_f16(
    const __half* __restrict__ A, const __half* __restrict__ Bt,
    float* __restrict__ C)
{
    __shared__ __align__(16) unsigned char tiles[4 * STG64];

    const int t = threadIdx.x;
    const int w = t >> 5, lane = t & 31, g = lane >> 2, tig = lane & 3;
    const int wm = (w >> 1) * 32, wn = (w & 1) * 32;
    const int m0 = blockIdx.y * 64, n0 = blockIdx.x * 64;
    const int li = lane & 7, lj = lane >> 3;

    const unsigned asb = sptr(tiles);
    const unsigned bsb = asb + 2 * STG64;
    const unsigned adrA0 = asb + (wm + (lj & 1) * 8 + li) * RSTRIDE + (lj >> 1) * 16;
    const unsigned adrA1 = adrA0 + 16 * RSTRIDE;
    const unsigned adrB  = bsb + (wn + lj * 8 + li) * RSTRIDE;

    G64_DECL(A, Bt)
    float Co[2][4][4] = {};
    G64_MAINLOOP()

    #pragma unroll
    for (int mt = 0; mt < 2; mt++)
        #pragma unroll
        for (int nt = 0; nt < 4; nt++) {
            int r = m0 + wm + mt * 16 + g;
            int c = n0 + wn + nt * 8 + 2 * tig;
            *(float2*)&C[(size_t)r * DIM + c]       = make_float2(Co[mt][nt][0], Co[mt][nt][1]);
            *(float2*)&C[(size_t)(r + 8) * DIM + c] = make_float2(Co[mt][nt][2], Co[mt][nt][3]);
        }
}

// ---------------- fused attention: 64-query CTAs (R16, unchanged) ----------
#define AQS  12
#define AVSH 72
__global__ __launch_bounds__(128, 5) void attn_f16(
    const __half* __restrict__ gq, const __half* __restrict__ gk,
    const __half* __restrict__ gv, __half* __restrict__ gao)
{
    __shared__ unsigned Qs[64][AQS];
    __shared__ unsigned Ks[2][64][AQS];
    __shared__ __half   Vs[2][64][AVSH];

    const int t = threadIdx.x;
    const int w = t >> 5, lane = t & 31, g = lane >> 2, tig = lane & 3;
    const int wm = w * 16;
    const int bh = blockIdx.y, q0 = blockIdx.x * 64;
    const int li = lane & 7, lj = lane >> 3;

    const __half* qb = gq + (size_t)bh * SEQ * DKH;
    const __half* kb = gk + (size_t)bh * SEQ * DKH;
    const __half* vb = gv + (size_t)bh * SEQ * DVH;

    {
        int r = t >> 1, hf = t & 1;
        *(uint4*)&Qs[r][hf * 4] = *(const uint4*)&qb[(size_t)(q0 + r) * DKH + hf * 8];
    }

    const int kr = t >> 1, khf = t & 1;
    #define ATTN_LOAD(k0_, buf_) do {                                            \
        cpa16(sptr(&Ks[buf_][kr][khf*4]), &kb[(size_t)((k0_)+kr)*DKH + khf*8]);  \
        _Pragma("unroll")                                                        \
        for (int i_ = 0; i_ < 4; i_++) {                                         \
            int idx_ = t + i_ * 128;                                             \
            int r_ = idx_ >> 3, c_ = (idx_ & 7) * 8;                             \
            cpa16(sptr(&Vs[buf_][r_][c_]), &vb[(size_t)((k0_)+r_)*DVH + c_]);    \
        }                                                                        \
    } while(0)

    ATTN_LOAD(0, 0);
    CP_COMMIT();
    __syncthreads();

    unsigned aq[4];
    ldm4(aq, sptr(&Qs[wm + (lj & 1) * 8 + li][(lj >> 1) * 4]));

    const unsigned KBUF = 64 * AQS * 4, VBUF = 64 * AVSH * 2;
    const unsigned adrK = sptr(&Ks[0][lj * 8 + li][0]);
    const unsigned adrV = sptr(&Vs[0][(lj & 1) * 8 + li][(lj >> 1) * 8]);

    float Co[8][4] = {};

    const int NT = SEQ / 64;
    for (int kt = 0; kt < NT; kt++) {
        CP_WAIT0();
        __syncthreads();
        if (kt + 1 < NT) { ATTN_LOAD((kt + 1) * 64, (kt + 1) & 1); CP_COMMIT(); }
        const unsigned kbase = adrK + (kt & 1) * KBUF;
        const unsigned vbase = adrV + (kt & 1) * VBUF;

        unsigned sf[4][4];
        #pragma unroll
        for (int hh = 0; hh < 2; hh++) {
            float Cs[4][4] = {};
            unsigned b0[4], b1[4];
            ldm4(b0, kbase + hh * 32 * AQS * 4);
            ldm4(b1, kbase + hh * 32 * AQS * 4 + 16);
            #pragma unroll
            for (int nt = 0; nt < 4; nt++) {
                unsigned bA[2] = { b0[nt], b1[nt] };
                mma16(Cs[nt], aq, bA);
            }
            #pragma unroll
            for (int p = 0; p < 2; p++) {
                float r0 = Cs[2*p][0];   r0 = r0 > 0.f ? r0*r0 : 0.f;
                float r1 = Cs[2*p][1];   r1 = r1 > 0.f ? r1*r1 : 0.f;
                float r2 = Cs[2*p][2];   r2 = r2 > 0.f ? r2*r2 : 0.f;
                float r3 = Cs[2*p][3];   r3 = r3 > 0.f ? r3*r3 : 0.f;
                float r4 = Cs[2*p+1][0]; r4 = r4 > 0.f ? r4*r4 : 0.f;
                float r5 = Cs[2*p+1][1]; r5 = r5 > 0.f ? r5*r5 : 0.f;
                float r6 = Cs[2*p+1][2]; r6 = r6 > 0.f ? r6*r6 : 0.f;
                float r7 = Cs[2*p+1][3]; r7 = r7 > 0.f ? r7*r7 : 0.f;
                sf[hh*2 + p][0] = packh2(r0, r1);
                sf[hh*2 + p][1] = packh2(r2, r3);
                sf[hh*2 + p][2] = packh2(r4, r5);
                sf[hh*2 + p][3] = packh2(r6, r7);
            }
        }

        #pragma unroll
        for (int ks = 0; ks < 4; ks++) {
            const unsigned vk = vbase + ks * 16 * AVSH * 2;
            #pragma unroll
            for (int j = 0; j < 4; j++) {
                unsigned vv[4];
                ldm4t(vv, vk + j * 32);
                unsigned bA[2] = { vv[0], vv[1] };
                unsigned bB[2] = { vv[2], vv[3] };
                mma16(Co[2*j],     sf[ks], bA);
                mma16(Co[2*j + 1], sf[ks], bB);
            }
        }
    }

    float s0 = 0.f, s1 = 0.f;
    #pragma unroll
    for (int nt = 0; nt < 8; nt++) {
        s0 += Co[nt][0]*Co[nt][0] + Co[nt][1]*Co[nt][1];
        s1 += Co[nt][2]*Co[nt][2] + Co[nt][3]*Co[nt][3];
    }
    s0 += __shfl_xor_sync(~0u, s0, 1); s0 += __shfl_xor_sync(~0u, s0, 2);
    s1 += __shfl_xor_sync(~0u, s1, 1); s1 += __shfl_xor_sync(~0u, s1, 2);
    float n0s = sqrtf(s0), n1s = sqrtf(s1);
    float sc0 = tanhf(n0s) / fmaxf(n0s, 1e-12f);
    float sc1 = tanhf(n1s) / fmaxf(n1s, 1e-12f);

    const int b_ = bh >> 4, h_ = bh & 15;
    const int row0 = q0 + wm + g, row1 = row0 + 8;
    __half* d0 = gao + (size_t)(b_ * SEQ + row0) * OCOLS + h_ * DVH;
    __half* d1 = gao + (size_t)(b_ * SEQ + row1) * OCOLS + h_ * DVH;
    #pragma unroll
    for (int nt = 0; nt < 8; nt++) {
        int c = nt * 8 + 2 * tig;
        *(unsigned*)&d0[c] = packh2(Co[nt][0] * sc0, Co[nt][1] * sc0);
        *(unsigned*)&d1[c] = packh2(Co[nt][2] * sc1, Co[nt][3] * sc1);
    }
}

// ---------------- host launch ----------------
extern "C" void kernel_launch(void* const* d_in, const int* in_sizes, int n_in,
                              void* d_out, int out_size)
{
    const float *tokens = nullptr, *Wq = nullptr, *Wkv = nullptr, *Wout = nullptr;
    for (int i = 0; i < n_in; i++) {
        switch (in_sizes[i]) {
            case NTOK * DIM:   tokens = (const float*)d_in[i]; break;
            case DIM * QCOLS:  Wq     = (const float*)d_in[i]; break;
            case DIM * KVCOLS: Wkv    = (const float*)d_in[i]; break;
            case OCOLS * DIM:  Wout   = (const float*)d_in[i]; break;
        }
    }

    __half *tokh, *wc, *wot, *qn, *kn, *vh, *aoh;
    cudaGetSymbolAddress((void**)&tokh, g_tokh);
    cudaGetSymbolAddress((void**)&wc,   g_wc);
    cudaGetSymbolAddress((void**)&wot,  g_wot);
    cudaGetSymbolAddress((void**)&qn,   g_qn);
    cudaGetSymbolAddress((void**)&kn,   g_kn);
    cudaGetSymbolAddress((void**)&vh,   g_vh);
    cudaGetSymbolAddress((void**)&aoh,  g_aoh);

    prep_all<<<PREP_TOTAL, 256>>>(tokens, Wq, Wkv, Wout, tokh, wc, wot);

    proj_gemm<<<dim3(PCOLS/64, NTOK/64), 128>>>(tokh, wc, qn, kn, vh);

    attn_f16<<<dim3(SEQ/64, BATCH*NH), 128>>>(qn, kn, vh, aoh);

    gemm_f16<<<dim3(DIM/64, NTOK/64), 128>>>(aoh, wot, (float*)d_out);
}